// round 15
// baseline (speedup 1.0000x reference)
#include <cuda_runtime.h>
#include <cuda_bf16.h>
#include <cstdint>

#define NMAX 100000
#define EMAX 600000

// Scratch (static device globals — allocation-free per harness rules)
__device__ __align__(16) float g_ylr[NMAX * 128];  // projected [y_l | y_r]
__device__ __align__(16) float g_x[NMAX * 64];     // layer activations
__device__ __align__(16) unsigned short g_wth[128 * 128];  // W0 hi bf16, n-major [n][k]
__device__ __align__(16) unsigned short g_wtl[128 * 128];  // W0 lo bf16, n-major [n][k]
__device__ __align__(16) unsigned short g_wth1[64 * 64];   // W1 hi bf16, n-major [n][k]
__device__ __align__(16) unsigned short g_wtl1[64 * 64];   // W1 lo bf16, n-major [n][k]
__device__ int g_cnt[NMAX];
__device__ int g_off[NMAX];
__device__ int g_cur[NMAX];
__device__ int g_esrc[EMAX];
__device__ int g_bsum[512];

// ---------------------------------------------------------------------------
// CSR build
// ---------------------------------------------------------------------------
__global__ void zero_int(int* __restrict__ p, int n) {
    int i = blockIdx.x * blockDim.x + threadIdx.x;
    if (i < n) p[i] = 0;
}

__global__ void hist_kernel(const int* __restrict__ dst, int* __restrict__ cnt, int E) {
    int i = blockIdx.x * blockDim.x + threadIdx.x;
    if (i < E) atomicAdd(&cnt[dst[i]], 1);
}

__device__ __forceinline__ int block_exscan_512(int v, int tid, int* warp_sums, int* total) {
    int lane = tid & 31, wid = tid >> 5;
    int inc = v;
#pragma unroll
    for (int st = 1; st < 32; st <<= 1) {
        int t = __shfl_up_sync(0xFFFFFFFFu, inc, st);
        if (lane >= st) inc += t;
    }
    if (lane == 31) warp_sums[wid] = inc;
    __syncthreads();
    if (wid == 0) {
        int ws = (lane < 16) ? warp_sums[lane] : 0;
#pragma unroll
        for (int st = 1; st < 16; st <<= 1) {
            int t = __shfl_up_sync(0xFFFFFFFFu, ws, st);
            if (lane >= st) ws += t;
        }
        if (lane < 16) warp_sums[lane] = ws;
    }
    __syncthreads();
    int base = (wid > 0) ? warp_sums[wid - 1] : 0;
    if (total) *total = warp_sums[15];
    return base + inc - v;
}

__global__ void scan_block(const int* __restrict__ cnt, int* __restrict__ off,
                           int* __restrict__ bsum, int n) {
    __shared__ int ws[16];
    int i = blockIdx.x * 512 + threadIdx.x;
    int v = (i < n) ? cnt[i] : 0;
    int total;
    int ex = block_exscan_512(v, threadIdx.x, ws, &total);
    if (i < n) off[i] = ex;
    if (threadIdx.x == 0) bsum[blockIdx.x] = total;
}

__global__ void scan_sums(int* __restrict__ bsum, int nb) {
    __shared__ int ws[16];
    int v = (threadIdx.x < nb) ? bsum[threadIdx.x] : 0;
    int ex = block_exscan_512(v, threadIdx.x, ws, nullptr);
    if (threadIdx.x < nb) bsum[threadIdx.x] = ex;
}

__global__ void scan_add(int* __restrict__ off, const int* __restrict__ bsum,
                         int* __restrict__ cur, int n) {
    int i = blockIdx.x * 512 + threadIdx.x;
    if (i < n) {
        int o = off[i] + bsum[blockIdx.x];
        off[i] = o;
        cur[i] = o;
    }
}

__global__ void fill_kernel(const int* __restrict__ src, const int* __restrict__ dst,
                            int* __restrict__ cur, int* __restrict__ esrc, int E) {
    int e = blockIdx.x * blockDim.x + threadIdx.x;
    if (e < E) {
        int p = atomicAdd(&cur[dst[e]], 1);
        esrc[p] = src[e];
    }
}

// ---------------------------------------------------------------------------
// W conversions: combined [k][n] -> n-major bf16 hi/lo wt[n*K + k]
// ---------------------------------------------------------------------------
__global__ void cvt_w_kernel(const float* __restrict__ wl, const float* __restrict__ wr,
                             unsigned short* __restrict__ wth, unsigned short* __restrict__ wtl) {
    int i = blockIdx.x * blockDim.x + threadIdx.x;
    if (i >= 128 * 128) return;
    int nn = i >> 7, k = i & 127;
    float w = (nn < 64) ? wl[k * 64 + nn] : wr[k * 64 + (nn - 64)];
    __nv_bfloat16 h = __float2bfloat16(w);
    __nv_bfloat16 l = __float2bfloat16(w - __bfloat162float(h));
    wth[i] = *reinterpret_cast<unsigned short*>(&h);
    wtl[i] = *reinterpret_cast<unsigned short*>(&l);
}

__global__ void cvt_w1_kernel(const float* __restrict__ wl, const float* __restrict__ wr,
                              unsigned short* __restrict__ wth, unsigned short* __restrict__ wtl) {
    int i = blockIdx.x * blockDim.x + threadIdx.x;
    if (i >= 64 * 64) return;
    int nn = i >> 6, k = i & 63;
    float w = (nn < 32) ? wl[k * 32 + nn] : wr[k * 32 + (nn - 32)];
    __nv_bfloat16 h = __float2bfloat16(w);
    __nv_bfloat16 l = __float2bfloat16(w - __bfloat162float(h));
    wth[i] = *reinterpret_cast<unsigned short*>(&h);
    wtl[i] = *reinterpret_cast<unsigned short*>(&l);
}

// ---------------------------------------------------------------------------
// mma helpers
// ---------------------------------------------------------------------------
__device__ __forceinline__ void mma16816(float* d, const unsigned* a,
                                         unsigned b0, unsigned b1) {
    asm volatile(
        "mma.sync.aligned.m16n8k16.row.col.f32.bf16.bf16.f32 "
        "{%0,%1,%2,%3}, {%4,%5,%6,%7}, {%8,%9}, {%0,%1,%2,%3};"
        : "+f"(d[0]), "+f"(d[1]), "+f"(d[2]), "+f"(d[3])
        : "r"(a[0]), "r"(a[1]), "r"(a[2]), "r"(a[3]), "r"(b0), "r"(b1));
}

__device__ __forceinline__ unsigned pack2_hi(float a, float b) {
    __nv_bfloat162 t;
    t.x = __float2bfloat16(a);
    t.y = __float2bfloat16(b);
    return *reinterpret_cast<unsigned*>(&t);
}

// ---------------------------------------------------------------------------
// layer-0 tensor-core GEMM (persistent)
// ---------------------------------------------------------------------------
__global__ void __launch_bounds__(256, 2)
mma_proj0(const float* __restrict__ x, const unsigned short* __restrict__ wth,
          const unsigned short* __restrict__ wtl, float* __restrict__ ylr,
          int n, int ntiles) {
    constexpr int S = 136;
    extern __shared__ __align__(16) unsigned short smu[];
    unsigned short* sXh = smu;              // [64][S]
    unsigned short* sXl = sXh + 64 * S;
    unsigned short* sWh = sXl + 64 * S;     // n-major [128][S]
    unsigned short* sWl = sWh + 128 * S;

    const int tid = threadIdx.x;
    const int lane = tid & 31;
    const int warp = tid >> 5;
    const int warpm = warp >> 1;
    const int warpn = warp & 1;
    const int g = lane >> 2;
    const int t2 = (lane & 3) * 2;

    for (int idx = tid; idx < 128 * 16; idx += 256) {
        int r = idx >> 4, c = (idx & 15) * 8;
        *reinterpret_cast<uint4*>(&sWh[r * S + c]) =
            *reinterpret_cast<const uint4*>(&wth[r * 128 + c]);
        *reinterpret_cast<uint4*>(&sWl[r * S + c]) =
            *reinterpret_cast<const uint4*>(&wtl[r * 128 + c]);
    }

    float4 xf[8];
    auto load_x = [&](int tile) {
        const int nb = tile * 64;
        const int mrem = n - nb;
#pragma unroll
        for (int i = 0; i < 8; ++i) {
            int idx = tid + i * 256;
            int r = idx >> 5, cc = (idx & 31) * 4;
            float4 v = make_float4(0.f, 0.f, 0.f, 0.f);
            if (r < mrem)
                v = *reinterpret_cast<const float4*>(&x[(size_t)(nb + r) * 128 + cc]);
            xf[i] = v;
        }
    };

    int tile = blockIdx.x;
    if (tile < ntiles) load_x(tile);

    while (tile < ntiles) {
#pragma unroll
        for (int i = 0; i < 8; ++i) {
            int idx = tid + i * 256;
            int r = idx >> 5, cc = (idx & 31) * 4;
            float4 v = xf[i];
            __nv_bfloat16 h0 = __float2bfloat16(v.x), h1 = __float2bfloat16(v.y);
            __nv_bfloat16 h2 = __float2bfloat16(v.z), h3 = __float2bfloat16(v.w);
            uint2 ph, pl;
            __nv_bfloat162 t;
            t.x = h0; t.y = h1; ph.x = *reinterpret_cast<unsigned*>(&t);
            t.x = h2; t.y = h3; ph.y = *reinterpret_cast<unsigned*>(&t);
            pl.x = pack2_hi(v.x - __bfloat162float(h0), v.y - __bfloat162float(h1));
            pl.y = pack2_hi(v.z - __bfloat162float(h2), v.w - __bfloat162float(h3));
            *reinterpret_cast<uint2*>(&sXh[r * S + cc]) = ph;
            *reinterpret_cast<uint2*>(&sXl[r * S + cc]) = pl;
        }
        __syncthreads();

        const int nb = tile * 64;
        const int next = tile + gridDim.x;
        if (next < ntiles) load_x(next);

        float acc[8][4];
#pragma unroll
        for (int nt = 0; nt < 8; ++nt)
#pragma unroll
            for (int t = 0; t < 4; ++t) acc[nt][t] = 0.f;

#pragma unroll
        for (int s = 0; s < 8; ++s) {
            const int k0 = s * 16;
            unsigned ah[4], al[4];
            {
                int r = warpm * 16 + g;
                ah[0] = *reinterpret_cast<const unsigned*>(&sXh[r * S + k0 + t2]);
                ah[1] = *reinterpret_cast<const unsigned*>(&sXh[(r + 8) * S + k0 + t2]);
                ah[2] = *reinterpret_cast<const unsigned*>(&sXh[r * S + k0 + t2 + 8]);
                ah[3] = *reinterpret_cast<const unsigned*>(&sXh[(r + 8) * S + k0 + t2 + 8]);
                al[0] = *reinterpret_cast<const unsigned*>(&sXl[r * S + k0 + t2]);
                al[1] = *reinterpret_cast<const unsigned*>(&sXl[(r + 8) * S + k0 + t2]);
                al[2] = *reinterpret_cast<const unsigned*>(&sXl[r * S + k0 + t2 + 8]);
                al[3] = *reinterpret_cast<const unsigned*>(&sXl[(r + 8) * S + k0 + t2 + 8]);
            }
#pragma unroll
            for (int nt = 0; nt < 8; ++nt) {
                int nn = warpn * 64 + nt * 8 + g;
                unsigned bh0 = *reinterpret_cast<const unsigned*>(&sWh[nn * S + k0 + t2]);
                unsigned bh1 = *reinterpret_cast<const unsigned*>(&sWh[nn * S + k0 + t2 + 8]);
                unsigned bl0 = *reinterpret_cast<const unsigned*>(&sWl[nn * S + k0 + t2]);
                unsigned bl1 = *reinterpret_cast<const unsigned*>(&sWl[nn * S + k0 + t2 + 8]);
                mma16816(acc[nt], ah, bh0, bh1);
                mma16816(acc[nt], al, bh0, bh1);
                mma16816(acc[nt], ah, bl0, bl1);
            }
        }

#pragma unroll
        for (int nt = 0; nt < 8; ++nt) {
            int col = warpn * 64 + nt * 8 + t2;
            int node0 = nb + warpm * 16 + g;
            int node1 = node0 + 8;
            if (node0 < n) {
                float2 v = make_float2(acc[nt][0], acc[nt][1]);
                *reinterpret_cast<float2*>(&ylr[(size_t)node0 * 128 + col]) = v;
            }
            if (node1 < n) {
                float2 v = make_float2(acc[nt][2], acc[nt][3]);
                *reinterpret_cast<float2*>(&ylr[(size_t)node1 * 128 + col]) = v;
            }
        }

        __syncthreads();
        tile = next;
    }
}

// ---------------------------------------------------------------------------
// layer-1 tensor-core GEMM (persistent)
// ---------------------------------------------------------------------------
__global__ void __launch_bounds__(256, 3)
mma_proj1(const float* __restrict__ x, const unsigned short* __restrict__ wth,
          const unsigned short* __restrict__ wtl, float* __restrict__ ylr,
          int n, int ntiles) {
    constexpr int S = 72;
    extern __shared__ __align__(16) unsigned short smu[];
    unsigned short* sXh = smu;              // [64][S]
    unsigned short* sXl = sXh + 64 * S;
    unsigned short* sWh = sXl + 64 * S;     // n-major [64][S]
    unsigned short* sWl = sWh + 64 * S;

    const int tid = threadIdx.x;
    const int lane = tid & 31;
    const int warp = tid >> 5;
    const int warpm = warp >> 1;
    const int warpn = warp & 1;
    const int g = lane >> 2;
    const int t2 = (lane & 3) * 2;

    for (int idx = tid; idx < 64 * 8; idx += 256) {
        int r = idx >> 3, c = (idx & 7) * 8;
        *reinterpret_cast<uint4*>(&sWh[r * S + c]) =
            *reinterpret_cast<const uint4*>(&wth[r * 64 + c]);
        *reinterpret_cast<uint4*>(&sWl[r * S + c]) =
            *reinterpret_cast<const uint4*>(&wtl[r * 64 + c]);
    }

    float4 xf[4];
    auto load_x = [&](int tile) {
        const int nb = tile * 64;
        const int mrem = n - nb;
#pragma unroll
        for (int i = 0; i < 4; ++i) {
            int idx = tid + i * 256;
            int r = idx >> 4, cc = (idx & 15) * 4;
            float4 v = make_float4(0.f, 0.f, 0.f, 0.f);
            if (r < mrem)
                v = *reinterpret_cast<const float4*>(&x[(size_t)(nb + r) * 64 + cc]);
            xf[i] = v;
        }
    };

    int tile = blockIdx.x;
    if (tile < ntiles) load_x(tile);

    while (tile < ntiles) {
#pragma unroll
        for (int i = 0; i < 4; ++i) {
            int idx = tid + i * 256;
            int r = idx >> 4, cc = (idx & 15) * 4;
            float4 v = xf[i];
            __nv_bfloat16 h0 = __float2bfloat16(v.x), h1 = __float2bfloat16(v.y);
            __nv_bfloat16 h2 = __float2bfloat16(v.z), h3 = __float2bfloat16(v.w);
            uint2 ph, pl;
            __nv_bfloat162 t;
            t.x = h0; t.y = h1; ph.x = *reinterpret_cast<unsigned*>(&t);
            t.x = h2; t.y = h3; ph.y = *reinterpret_cast<unsigned*>(&t);
            pl.x = pack2_hi(v.x - __bfloat162float(h0), v.y - __bfloat162float(h1));
            pl.y = pack2_hi(v.z - __bfloat162float(h2), v.w - __bfloat162float(h3));
            *reinterpret_cast<uint2*>(&sXh[r * S + cc]) = ph;
            *reinterpret_cast<uint2*>(&sXl[r * S + cc]) = pl;
        }
        __syncthreads();

        const int nb = tile * 64;
        const int next = tile + gridDim.x;
        if (next < ntiles) load_x(next);

        float acc[4][4];
#pragma unroll
        for (int nt = 0; nt < 4; ++nt)
#pragma unroll
            for (int t = 0; t < 4; ++t) acc[nt][t] = 0.f;

#pragma unroll
        for (int s = 0; s < 4; ++s) {
            const int k0 = s * 16;
            unsigned ah[4], al[4];
            {
                int r = warpm * 16 + g;
                ah[0] = *reinterpret_cast<const unsigned*>(&sXh[r * S + k0 + t2]);
                ah[1] = *reinterpret_cast<const unsigned*>(&sXh[(r + 8) * S + k0 + t2]);
                ah[2] = *reinterpret_cast<const unsigned*>(&sXh[r * S + k0 + t2 + 8]);
                ah[3] = *reinterpret_cast<const unsigned*>(&sXh[(r + 8) * S + k0 + t2 + 8]);
                al[0] = *reinterpret_cast<const unsigned*>(&sXl[r * S + k0 + t2]);
                al[1] = *reinterpret_cast<const unsigned*>(&sXl[(r + 8) * S + k0 + t2]);
                al[2] = *reinterpret_cast<const unsigned*>(&sXl[r * S + k0 + t2 + 8]);
                al[3] = *reinterpret_cast<const unsigned*>(&sXl[(r + 8) * S + k0 + t2 + 8]);
            }
#pragma unroll
            for (int nt = 0; nt < 4; ++nt) {
                int nn = warpn * 32 + nt * 8 + g;
                unsigned bh0 = *reinterpret_cast<const unsigned*>(&sWh[nn * S + k0 + t2]);
                unsigned bh1 = *reinterpret_cast<const unsigned*>(&sWh[nn * S + k0 + t2 + 8]);
                unsigned bl0 = *reinterpret_cast<const unsigned*>(&sWl[nn * S + k0 + t2]);
                unsigned bl1 = *reinterpret_cast<const unsigned*>(&sWl[nn * S + k0 + t2 + 8]);
                mma16816(acc[nt], ah, bh0, bh1);
                mma16816(acc[nt], al, bh0, bh1);
                mma16816(acc[nt], ah, bl0, bl1);
            }
        }

#pragma unroll
        for (int nt = 0; nt < 4; ++nt) {
            int col = warpn * 32 + nt * 8 + t2;
            int node0 = nb + warpm * 16 + g;
            int node1 = node0 + 8;
            if (node0 < n) {
                float2 v = make_float2(acc[nt][0], acc[nt][1]);
                *reinterpret_cast<float2*>(&ylr[(size_t)node0 * 64 + col]) = v;
            }
            if (node1 < n) {
                float2 v = make_float2(acc[nt][2], acc[nt][3]);
                *reinterpret_cast<float2*>(&ylr[(size_t)node1 * 64 + col]) = v;
            }
        }

        __syncthreads();
        tile = next;
    }
}

// ---------------------------------------------------------------------------
// per-node projection for small layers
// ---------------------------------------------------------------------------
template <int K, int F>
__global__ void proj_pernode(const float* __restrict__ x, const float* __restrict__ wl,
                             const float* __restrict__ wr, float* __restrict__ ylr, int n) {
    constexpr int NC = 2 * F;
    __shared__ float sB[K * NC];
    for (int i = threadIdx.x; i < K * NC; i += blockDim.x) {
        int k = i / NC, j = i % NC;
        sB[i] = (j < F) ? wl[k * F + j] : wr[k * F + (j - F)];
    }
    __syncthreads();

    int node = blockIdx.x * blockDim.x + threadIdx.x;
    if (node >= n) return;

    float xv[K];
    const float4* xr = reinterpret_cast<const float4*>(x + (size_t)node * K);
#pragma unroll
    for (int c = 0; c < K / 4; ++c) {
        float4 v = xr[c];
        xv[c * 4 + 0] = v.x; xv[c * 4 + 1] = v.y; xv[c * 4 + 2] = v.z; xv[c * 4 + 3] = v.w;
    }
    float acc[NC];
#pragma unroll
    for (int j = 0; j < NC; ++j) acc[j] = 0.f;
#pragma unroll
    for (int k = 0; k < K; ++k) {
        float a = xv[k];
#pragma unroll
        for (int j = 0; j < NC; ++j) acc[j] = fmaf(a, sB[k * NC + j], acc[j]);
    }
    float4* o = reinterpret_cast<float4*>(ylr + (size_t)node * NC);
#pragma unroll
    for (int c = 0; c < NC / 4; ++c)
        o[c] = make_float4(acc[c * 4], acc[c * 4 + 1], acc[c * 4 + 2], acc[c * 4 + 3]);
}

__global__ void proj3_pernode(const float* __restrict__ x, const float* __restrict__ wl,
                              const float* __restrict__ wr, float* __restrict__ ylr3, int n) {
    __shared__ float swl[16 * 9];
    __shared__ float swr[16 * 9];
    for (int i = threadIdx.x; i < 144; i += blockDim.x) {
        swl[i] = wl[i];
        swr[i] = wr[i];
    }
    __syncthreads();

    int node = blockIdx.x * blockDim.x + threadIdx.x;
    if (node >= n) return;

    float xv[16];
    const float4* xr = reinterpret_cast<const float4*>(x + (size_t)node * 16);
#pragma unroll
    for (int c = 0; c < 4; ++c) {
        float4 v = xr[c];
        xv[c * 4 + 0] = v.x; xv[c * 4 + 1] = v.y; xv[c * 4 + 2] = v.z; xv[c * 4 + 3] = v.w;
    }
    float al[9], ar[9];
#pragma unroll
    for (int j = 0; j < 9; ++j) { al[j] = 0.f; ar[j] = 0.f; }
#pragma unroll
    for (int k = 0; k < 16; ++k) {
        float a = xv[k];
#pragma unroll
        for (int j = 0; j < 9; ++j) {
            al[j] = fmaf(a, swl[k * 9 + j], al[j]);
            ar[j] = fmaf(a, swr[k * 9 + j], ar[j]);
        }
    }
    float4* o = reinterpret_cast<float4*>(ylr3 + (size_t)node * 32);
    o[0] = make_float4(al[0], al[1], al[2], al[3]);
    o[1] = make_float4(al[4], al[5], al[6], al[7]);
    o[2] = make_float4(al[8], 0.f, 0.f, 0.f);
    o[3] = make_float4(0.f, 0.f, 0.f, 0.f);
    o[4] = make_float4(ar[0], ar[1], ar[2], ar[3]);
    o[5] = make_float4(ar[4], ar[5], ar[6], ar[7]);
    ylr3[(size_t)node * 32 + 24] = ar[8];
}

// ---------------------------------------------------------------------------
// gather + combine (fused): warp per node, shfl-distributed edge indices,
// fully unrolled main loop for maximum MLP.
// ---------------------------------------------------------------------------
template <int F, bool RELU>
__global__ void gather_combine(const float* __restrict__ ylr, const int* __restrict__ esrc,
                               const int* __restrict__ off, const int* __restrict__ cnt,
                               const float* __restrict__ bias, float* __restrict__ out, int n) {
    constexpr int CH = F / 4;
    constexpr int EPW = 32 / CH;
    int w = (blockIdx.x * blockDim.x + threadIdx.x) >> 5;
    if (w >= n) return;
    int lane = threadIdx.x & 31;
    int c = lane % CH, g = lane / CH;
    int start = __ldg(off + w), deg = __ldg(cnt + w);

    int eidx = 0;
    if (lane < deg) eidx = __ldg(esrc + start + lane);

    float4 acc = make_float4(0.f, 0.f, 0.f, 0.f);
    const float4* y4 = reinterpret_cast<const float4*>(ylr);
    int dmain = deg < 32 ? deg : 32;

#pragma unroll
    for (int j = 0; j < 32; j += EPW) {
        int jj = j + g;
        if (j >= dmain) break;
        int src_lane = jj < 31 ? jj : 31;
        int s = __shfl_sync(0xFFFFFFFFu, eidx, src_lane);
        if (jj < dmain) {
            float4 v = y4[(size_t)s * (F / 2) + c];
            acc.x += v.x; acc.y += v.y; acc.z += v.z; acc.w += v.w;
        }
    }
    for (int j = 32 + g; j < deg; j += EPW) {
        int s = __ldg(esrc + start + j);
        float4 v = y4[(size_t)s * (F / 2) + c];
        acc.x += v.x; acc.y += v.y; acc.z += v.z; acc.w += v.w;
    }

#pragma unroll
    for (int st = 16; st >= CH; st >>= 1) {
        acc.x += __shfl_xor_sync(0xFFFFFFFFu, acc.x, st);
        acc.y += __shfl_xor_sync(0xFFFFFFFFu, acc.y, st);
        acc.z += __shfl_xor_sync(0xFFFFFFFFu, acc.z, st);
        acc.w += __shfl_xor_sync(0xFFFFFFFFu, acc.w, st);
    }
    if (lane < CH) {
        float iv = __frcp_rn(fmaxf((float)deg, 1.0f));
        float4 r = y4[(size_t)w * (F / 2) + (F / 4) + c];
        float4 b = reinterpret_cast<const float4*>(bias)[c];
        float4 v;
        v.x = fmaf(acc.x, iv, r.x) + b.x;
        v.y = fmaf(acc.y, iv, r.y) + b.y;
        v.z = fmaf(acc.z, iv, r.z) + b.z;
        v.w = fmaf(acc.w, iv, r.w) + b.w;
        if (RELU) {
            v.x = fmaxf(v.x, 0.f); v.y = fmaxf(v.y, 0.f);
            v.z = fmaxf(v.z, 0.f); v.w = fmaxf(v.w, 0.f);
        }
        reinterpret_cast<float4*>(out)[(size_t)w * CH + c] = v;
    }
}

__global__ void gather9(const float* __restrict__ ylr3, const int* __restrict__ esrc,
                        const int* __restrict__ off, const int* __restrict__ cnt,
                        const float* __restrict__ bias, float* __restrict__ out, int n) {
    int w = (blockIdx.x * blockDim.x + threadIdx.x) >> 5;
    if (w >= n) return;
    int lane = threadIdx.x & 31;
    int c = lane % 4, g = lane / 4;
    int start = __ldg(off + w), deg = __ldg(cnt + w);

    int eidx = 0;
    if (lane < deg) eidx = __ldg(esrc + start + lane);

    float4 acc = make_float4(0.f, 0.f, 0.f, 0.f);
    const float4* y4 = reinterpret_cast<const float4*>(ylr3);
    int dmain = deg < 32 ? deg : 32;

#pragma unroll
    for (int j = 0; j < 32; j += 8) {
        int jj = j + g;
        if (j >= dmain) break;
        int src_lane = jj < 31 ? jj : 31;
        int s = __shfl_sync(0xFFFFFFFFu, eidx, src_lane);
        if (jj < dmain) {
            float4 v = y4[(size_t)s * 8 + c];
            acc.x += v.x; acc.y += v.y; acc.z += v.z; acc.w += v.w;
        }
    }
    for (int j = 32 + g; j < deg; j += 8) {
        int s = __ldg(esrc + start + j);
        float4 v = y4[(size_t)s * 8 + c];
        acc.x += v.x; acc.y += v.y; acc.z += v.z; acc.w += v.w;
    }

#pragma unroll
    for (int st = 16; st >= 4; st >>= 1) {
        acc.x += __shfl_xor_sync(0xFFFFFFFFu, acc.x, st);
        acc.y += __shfl_xor_sync(0xFFFFFFFFu, acc.y, st);
        acc.z += __shfl_xor_sync(0xFFFFFFFFu, acc.z, st);
        acc.w += __shfl_xor_sync(0xFFFFFFFFu, acc.w, st);
    }
    if (lane < 4) {
        float iv = __frcp_rn(fmaxf((float)deg, 1.0f));
        float a[4] = {acc.x, acc.y, acc.z, acc.w};
#pragma unroll
        for (int t = 0; t < 4; ++t) {
            int j = c * 4 + t;
            if (j < 9) {
                float yr = ylr3[(size_t)w * 32 + 16 + j];
                out[(size_t)w * 9 + j] = fmaf(a[t], iv, yr + __ldg(bias + j));
            }
        }
    }
}

// ---------------------------------------------------------------------------
// launch
// ---------------------------------------------------------------------------
extern "C" void kernel_launch(void* const* d_in, const int* in_sizes, int n_in,
                              void* d_out, int out_size) {
    const float* emb = (const float*)d_in[0];
    const int* ei = (const int*)d_in[1];
    const float* wl0 = (const float*)d_in[3];
    const float* wr0 = (const float*)d_in[4];
    const float* b0  = (const float*)d_in[5];
    const float* wl1 = (const float*)d_in[6];
    const float* wr1 = (const float*)d_in[7];
    const float* b1  = (const float*)d_in[8];
    const float* wl2 = (const float*)d_in[9];
    const float* wr2 = (const float*)d_in[10];
    const float* b2  = (const float*)d_in[11];
    const float* wl3 = (const float*)d_in[12];
    const float* wr3 = (const float*)d_in[13];
    const float* b3  = (const float*)d_in[14];
    float* out = (float*)d_out;

    const int n = in_sizes[0] / 128;
    const int E = in_sizes[1] / 2;
    const int* src = ei;
    const int* dst = ei + E;

    float *ylr, *xbuf;
    unsigned short *wth, *wtl, *wth1, *wtl1;
    int *cnt, *off, *cur, *esrc, *bsum;
    cudaGetSymbolAddress((void**)&ylr, g_ylr);
    cudaGetSymbolAddress((void**)&xbuf, g_x);
    cudaGetSymbolAddress((void**)&wth, g_wth);
    cudaGetSymbolAddress((void**)&wtl, g_wtl);
    cudaGetSymbolAddress((void**)&wth1, g_wth1);
    cudaGetSymbolAddress((void**)&wtl1, g_wtl1);
    cudaGetSymbolAddress((void**)&cnt, g_cnt);
    cudaGetSymbolAddress((void**)&off, g_off);
    cudaGetSymbolAddress((void**)&cur, g_cur);
    cudaGetSymbolAddress((void**)&esrc, g_esrc);
    cudaGetSymbolAddress((void**)&bsum, g_bsum);

    auto cdiv = [](int a, int b) { return (a + b - 1) / b; };
    const int GB = 512;  // gather block size
    const int nb = cdiv(n, 512);

    const int SM_MMA0 = (2 * 64 * 136 + 2 * 128 * 136) * 2;  // 104448
    const int SM_MMA1 = (4 * 64 * 72) * 2;                   // 36864
    cudaFuncSetAttribute((const void*)mma_proj0,
                         cudaFuncAttributeMaxDynamicSharedMemorySize, SM_MMA0);
    cudaFuncSetAttribute((const void*)mma_proj1,
                         cudaFuncAttributeMaxDynamicSharedMemorySize, SM_MMA1);

    static cudaStream_t s2 = nullptr;
    static cudaEvent_t evFork = nullptr, evJoin = nullptr;
    if (!s2) {
        cudaStreamCreateWithFlags(&s2, cudaStreamNonBlocking);
        cudaEventCreateWithFlags(&evFork, cudaEventDisableTiming);
        cudaEventCreateWithFlags(&evJoin, cudaEventDisableTiming);
    }

    // ---- fork: CSR build + W1 conversion on s2 (hidden under proj0) ----
    cudaEventRecord(evFork, 0);
    cudaStreamWaitEvent(s2, evFork, 0);

    cvt_w1_kernel<<<16, 256, 0, s2>>>(wl1, wr1, wth1, wtl1);
    zero_int<<<cdiv(n, 512), 512, 0, s2>>>(cnt, n);
    hist_kernel<<<cdiv(E, 512), 512, 0, s2>>>(dst, cnt, E);
    scan_block<<<nb, 512, 0, s2>>>(cnt, off, bsum, n);
    scan_sums<<<1, 512, 0, s2>>>(bsum, nb);
    scan_add<<<nb, 512, 0, s2>>>(off, bsum, cur, n);
    fill_kernel<<<cdiv(E, 512), 512, 0, s2>>>(src, dst, cur, esrc, E);
    cudaEventRecord(evJoin, s2);

    // ---- main: layer-0 tensor-core GEMM (persistent) ----
    cvt_w_kernel<<<64, 256>>>(wl0, wr0, wth, wtl);
    mma_proj0<<<296, 256, SM_MMA0>>>(emb, wth, wtl, ylr, n, cdiv(n, 64));

    // ---- join ----
    cudaStreamWaitEvent(0, evJoin, 0);

    gather_combine<64, true><<<cdiv(n * 32, GB), GB>>>(ylr, esrc, off, cnt, b0, xbuf, n);

    mma_proj1<<<444, 256, SM_MMA1>>>(xbuf, wth1, wtl1, ylr, n, cdiv(n, 64));
    gather_combine<32, true><<<cdiv(n * 32, GB), GB>>>(ylr, esrc, off, cnt, b1, xbuf, n);

    proj_pernode<32, 16><<<cdiv(n, 256), 256>>>(xbuf, wl2, wr2, ylr, n);
    gather_combine<16, true><<<cdiv(n * 32, GB), GB>>>(ylr, esrc, off, cnt, b2, xbuf, n);

    proj3_pernode<<<cdiv(n, 256), 256>>>(xbuf, wl3, wr3, ylr, n);
    gather9<<<cdiv(n * 32, GB), GB>>>(ylr, esrc, off, cnt, b3, out, n);
}

// round 16
// speedup vs baseline: 1.0734x; 1.0734x over previous
#include <cuda_runtime.h>
#include <cuda_bf16.h>
#include <cstdint>

#define NMAX 100000
#define EMAX 600000

// Scratch (static device globals — allocation-free per harness rules)
__device__ __align__(16) float g_ylr[NMAX * 128];  // projected [y_l | y_r]
__device__ __align__(16) float g_x[NMAX * 64];     // layer activations
__device__ __align__(16) unsigned short g_wth[128 * 128];  // W0 hi bf16, n-major [n][k]
__device__ __align__(16) unsigned short g_wtl[128 * 128];  // W0 lo bf16, n-major [n][k]
__device__ __align__(16) unsigned short g_wth1[64 * 64];   // W1 hi bf16, n-major [n][k]
__device__ __align__(16) unsigned short g_wtl1[64 * 64];   // W1 lo bf16, n-major [n][k]
__device__ int g_cnt[NMAX];
__device__ int g_off[NMAX];
__device__ int g_cur[NMAX];
__device__ int g_esrc[EMAX];
__device__ int g_bsum[512];

// ---------------------------------------------------------------------------
// CSR build
// ---------------------------------------------------------------------------
__global__ void zero_int(int* __restrict__ p, int n) {
    int i = blockIdx.x * blockDim.x + threadIdx.x;
    if (i < n) p[i] = 0;
}

__global__ void hist_kernel(const int* __restrict__ dst, int* __restrict__ cnt, int E) {
    int i = blockIdx.x * blockDim.x + threadIdx.x;
    if (i < E) atomicAdd(&cnt[dst[i]], 1);
}

__device__ __forceinline__ int block_exscan_512(int v, int tid, int* warp_sums, int* total) {
    int lane = tid & 31, wid = tid >> 5;
    int inc = v;
#pragma unroll
    for (int st = 1; st < 32; st <<= 1) {
        int t = __shfl_up_sync(0xFFFFFFFFu, inc, st);
        if (lane >= st) inc += t;
    }
    if (lane == 31) warp_sums[wid] = inc;
    __syncthreads();
    if (wid == 0) {
        int ws = (lane < 16) ? warp_sums[lane] : 0;
#pragma unroll
        for (int st = 1; st < 16; st <<= 1) {
            int t = __shfl_up_sync(0xFFFFFFFFu, ws, st);
            if (lane >= st) ws += t;
        }
        if (lane < 16) warp_sums[lane] = ws;
    }
    __syncthreads();
    int base = (wid > 0) ? warp_sums[wid - 1] : 0;
    if (total) *total = warp_sums[15];
    return base + inc - v;
}

__global__ void scan_block(const int* __restrict__ cnt, int* __restrict__ off,
                           int* __restrict__ bsum, int n) {
    __shared__ int ws[16];
    int i = blockIdx.x * 512 + threadIdx.x;
    int v = (i < n) ? cnt[i] : 0;
    int total;
    int ex = block_exscan_512(v, threadIdx.x, ws, &total);
    if (i < n) off[i] = ex;
    if (threadIdx.x == 0) bsum[blockIdx.x] = total;
}

__global__ void scan_sums(int* __restrict__ bsum, int nb) {
    __shared__ int ws[16];
    int v = (threadIdx.x < nb) ? bsum[threadIdx.x] : 0;
    int ex = block_exscan_512(v, threadIdx.x, ws, nullptr);
    if (threadIdx.x < nb) bsum[threadIdx.x] = ex;
}

__global__ void scan_add(int* __restrict__ off, const int* __restrict__ bsum,
                         int* __restrict__ cur, int n) {
    int i = blockIdx.x * 512 + threadIdx.x;
    if (i < n) {
        int o = off[i] + bsum[blockIdx.x];
        off[i] = o;
        cur[i] = o;
    }
}

__global__ void fill_kernel(const int* __restrict__ src, const int* __restrict__ dst,
                            int* __restrict__ cur, int* __restrict__ esrc, int E) {
    int e = blockIdx.x * blockDim.x + threadIdx.x;
    if (e < E) {
        int p = atomicAdd(&cur[dst[e]], 1);
        esrc[p] = src[e];
    }
}

// ---------------------------------------------------------------------------
// W conversions: combined [k][n] -> n-major bf16 hi/lo wt[n*K + k]
// ---------------------------------------------------------------------------
__global__ void cvt_w_kernel(const float* __restrict__ wl, const float* __restrict__ wr,
                             unsigned short* __restrict__ wth, unsigned short* __restrict__ wtl) {
    int i = blockIdx.x * blockDim.x + threadIdx.x;
    if (i >= 128 * 128) return;
    int nn = i >> 7, k = i & 127;
    float w = (nn < 64) ? wl[k * 64 + nn] : wr[k * 64 + (nn - 64)];
    __nv_bfloat16 h = __float2bfloat16(w);
    __nv_bfloat16 l = __float2bfloat16(w - __bfloat162float(h));
    wth[i] = *reinterpret_cast<unsigned short*>(&h);
    wtl[i] = *reinterpret_cast<unsigned short*>(&l);
}

__global__ void cvt_w1_kernel(const float* __restrict__ wl, const float* __restrict__ wr,
                              unsigned short* __restrict__ wth, unsigned short* __restrict__ wtl) {
    int i = blockIdx.x * blockDim.x + threadIdx.x;
    if (i >= 64 * 64) return;
    int nn = i >> 6, k = i & 63;
    float w = (nn < 32) ? wl[k * 32 + nn] : wr[k * 32 + (nn - 32)];
    __nv_bfloat16 h = __float2bfloat16(w);
    __nv_bfloat16 l = __float2bfloat16(w - __bfloat162float(h));
    wth[i] = *reinterpret_cast<unsigned short*>(&h);
    wtl[i] = *reinterpret_cast<unsigned short*>(&l);
}

// ---------------------------------------------------------------------------
// mma helpers
// ---------------------------------------------------------------------------
__device__ __forceinline__ void mma16816(float* d, const unsigned* a,
                                         unsigned b0, unsigned b1) {
    asm volatile(
        "mma.sync.aligned.m16n8k16.row.col.f32.bf16.bf16.f32 "
        "{%0,%1,%2,%3}, {%4,%5,%6,%7}, {%8,%9}, {%0,%1,%2,%3};"
        : "+f"(d[0]), "+f"(d[1]), "+f"(d[2]), "+f"(d[3])
        : "r"(a[0]), "r"(a[1]), "r"(a[2]), "r"(a[3]), "r"(b0), "r"(b1));
}

__device__ __forceinline__ unsigned pack2_hi(float a, float b) {
    __nv_bfloat162 t;
    t.x = __float2bfloat16(a);
    t.y = __float2bfloat16(b);
    return *reinterpret_cast<unsigned*>(&t);
}

// ---------------------------------------------------------------------------
// layer-0 tensor-core GEMM (persistent)
// ---------------------------------------------------------------------------
__global__ void __launch_bounds__(256, 2)
mma_proj0(const float* __restrict__ x, const unsigned short* __restrict__ wth,
          const unsigned short* __restrict__ wtl, float* __restrict__ ylr,
          int n, int ntiles) {
    constexpr int S = 136;
    extern __shared__ __align__(16) unsigned short smu[];
    unsigned short* sXh = smu;              // [64][S]
    unsigned short* sXl = sXh + 64 * S;
    unsigned short* sWh = sXl + 64 * S;     // n-major [128][S]
    unsigned short* sWl = sWh + 128 * S;

    const int tid = threadIdx.x;
    const int lane = tid & 31;
    const int warp = tid >> 5;
    const int warpm = warp >> 1;
    const int warpn = warp & 1;
    const int g = lane >> 2;
    const int t2 = (lane & 3) * 2;

    for (int idx = tid; idx < 128 * 16; idx += 256) {
        int r = idx >> 4, c = (idx & 15) * 8;
        *reinterpret_cast<uint4*>(&sWh[r * S + c]) =
            *reinterpret_cast<const uint4*>(&wth[r * 128 + c]);
        *reinterpret_cast<uint4*>(&sWl[r * S + c]) =
            *reinterpret_cast<const uint4*>(&wtl[r * 128 + c]);
    }

    float4 xf[8];
    auto load_x = [&](int tile) {
        const int nb = tile * 64;
        const int mrem = n - nb;
#pragma unroll
        for (int i = 0; i < 8; ++i) {
            int idx = tid + i * 256;
            int r = idx >> 5, cc = (idx & 31) * 4;
            float4 v = make_float4(0.f, 0.f, 0.f, 0.f);
            if (r < mrem)
                v = *reinterpret_cast<const float4*>(&x[(size_t)(nb + r) * 128 + cc]);
            xf[i] = v;
        }
    };

    int tile = blockIdx.x;
    if (tile < ntiles) load_x(tile);

    while (tile < ntiles) {
#pragma unroll
        for (int i = 0; i < 8; ++i) {
            int idx = tid + i * 256;
            int r = idx >> 5, cc = (idx & 31) * 4;
            float4 v = xf[i];
            __nv_bfloat16 h0 = __float2bfloat16(v.x), h1 = __float2bfloat16(v.y);
            __nv_bfloat16 h2 = __float2bfloat16(v.z), h3 = __float2bfloat16(v.w);
            uint2 ph, pl;
            __nv_bfloat162 t;
            t.x = h0; t.y = h1; ph.x = *reinterpret_cast<unsigned*>(&t);
            t.x = h2; t.y = h3; ph.y = *reinterpret_cast<unsigned*>(&t);
            pl.x = pack2_hi(v.x - __bfloat162float(h0), v.y - __bfloat162float(h1));
            pl.y = pack2_hi(v.z - __bfloat162float(h2), v.w - __bfloat162float(h3));
            *reinterpret_cast<uint2*>(&sXh[r * S + cc]) = ph;
            *reinterpret_cast<uint2*>(&sXl[r * S + cc]) = pl;
        }
        __syncthreads();

        const int nb = tile * 64;
        const int next = tile + gridDim.x;
        if (next < ntiles) load_x(next);

        float acc[8][4];
#pragma unroll
        for (int nt = 0; nt < 8; ++nt)
#pragma unroll
            for (int t = 0; t < 4; ++t) acc[nt][t] = 0.f;

#pragma unroll
        for (int s = 0; s < 8; ++s) {
            const int k0 = s * 16;
            unsigned ah[4], al[4];
            {
                int r = warpm * 16 + g;
                ah[0] = *reinterpret_cast<const unsigned*>(&sXh[r * S + k0 + t2]);
                ah[1] = *reinterpret_cast<const unsigned*>(&sXh[(r + 8) * S + k0 + t2]);
                ah[2] = *reinterpret_cast<const unsigned*>(&sXh[r * S + k0 + t2 + 8]);
                ah[3] = *reinterpret_cast<const unsigned*>(&sXh[(r + 8) * S + k0 + t2 + 8]);
                al[0] = *reinterpret_cast<const unsigned*>(&sXl[r * S + k0 + t2]);
                al[1] = *reinterpret_cast<const unsigned*>(&sXl[(r + 8) * S + k0 + t2]);
                al[2] = *reinterpret_cast<const unsigned*>(&sXl[r * S + k0 + t2 + 8]);
                al[3] = *reinterpret_cast<const unsigned*>(&sXl[(r + 8) * S + k0 + t2 + 8]);
            }
#pragma unroll
            for (int nt = 0; nt < 8; ++nt) {
                int nn = warpn * 64 + nt * 8 + g;
                unsigned bh0 = *reinterpret_cast<const unsigned*>(&sWh[nn * S + k0 + t2]);
                unsigned bh1 = *reinterpret_cast<const unsigned*>(&sWh[nn * S + k0 + t2 + 8]);
                unsigned bl0 = *reinterpret_cast<const unsigned*>(&sWl[nn * S + k0 + t2]);
                unsigned bl1 = *reinterpret_cast<const unsigned*>(&sWl[nn * S + k0 + t2 + 8]);
                mma16816(acc[nt], ah, bh0, bh1);
                mma16816(acc[nt], al, bh0, bh1);
                mma16816(acc[nt], ah, bl0, bl1);
            }
        }

#pragma unroll
        for (int nt = 0; nt < 8; ++nt) {
            int col = warpn * 64 + nt * 8 + t2;
            int node0 = nb + warpm * 16 + g;
            int node1 = node0 + 8;
            if (node0 < n) {
                float2 v = make_float2(acc[nt][0], acc[nt][1]);
                *reinterpret_cast<float2*>(&ylr[(size_t)node0 * 128 + col]) = v;
            }
            if (node1 < n) {
                float2 v = make_float2(acc[nt][2], acc[nt][3]);
                *reinterpret_cast<float2*>(&ylr[(size_t)node1 * 128 + col]) = v;
            }
        }

        __syncthreads();
        tile = next;
    }
}

// ---------------------------------------------------------------------------
// layer-1 tensor-core GEMM (persistent)
// ---------------------------------------------------------------------------
__global__ void __launch_bounds__(256, 3)
mma_proj1(const float* __restrict__ x, const unsigned short* __restrict__ wth,
          const unsigned short* __restrict__ wtl, float* __restrict__ ylr,
          int n, int ntiles) {
    constexpr int S = 72;
    extern __shared__ __align__(16) unsigned short smu[];
    unsigned short* sXh = smu;              // [64][S]
    unsigned short* sXl = sXh + 64 * S;
    unsigned short* sWh = sXl + 64 * S;     // n-major [64][S]
    unsigned short* sWl = sWh + 64 * S;

    const int tid = threadIdx.x;
    const int lane = tid & 31;
    const int warp = tid >> 5;
    const int warpm = warp >> 1;
    const int warpn = warp & 1;
    const int g = lane >> 2;
    const int t2 = (lane & 3) * 2;

    for (int idx = tid; idx < 64 * 8; idx += 256) {
        int r = idx >> 3, c = (idx & 7) * 8;
        *reinterpret_cast<uint4*>(&sWh[r * S + c]) =
            *reinterpret_cast<const uint4*>(&wth[r * 64 + c]);
        *reinterpret_cast<uint4*>(&sWl[r * S + c]) =
            *reinterpret_cast<const uint4*>(&wtl[r * 64 + c]);
    }

    float4 xf[4];
    auto load_x = [&](int tile) {
        const int nb = tile * 64;
        const int mrem = n - nb;
#pragma unroll
        for (int i = 0; i < 4; ++i) {
            int idx = tid + i * 256;
            int r = idx >> 4, cc = (idx & 15) * 4;
            float4 v = make_float4(0.f, 0.f, 0.f, 0.f);
            if (r < mrem)
                v = *reinterpret_cast<const float4*>(&x[(size_t)(nb + r) * 64 + cc]);
            xf[i] = v;
        }
    };

    int tile = blockIdx.x;
    if (tile < ntiles) load_x(tile);

    while (tile < ntiles) {
#pragma unroll
        for (int i = 0; i < 4; ++i) {
            int idx = tid + i * 256;
            int r = idx >> 4, cc = (idx & 15) * 4;
            float4 v = xf[i];
            __nv_bfloat16 h0 = __float2bfloat16(v.x), h1 = __float2bfloat16(v.y);
            __nv_bfloat16 h2 = __float2bfloat16(v.z), h3 = __float2bfloat16(v.w);
            uint2 ph, pl;
            __nv_bfloat162 t;
            t.x = h0; t.y = h1; ph.x = *reinterpret_cast<unsigned*>(&t);
            t.x = h2; t.y = h3; ph.y = *reinterpret_cast<unsigned*>(&t);
            pl.x = pack2_hi(v.x - __bfloat162float(h0), v.y - __bfloat162float(h1));
            pl.y = pack2_hi(v.z - __bfloat162float(h2), v.w - __bfloat162float(h3));
            *reinterpret_cast<uint2*>(&sXh[r * S + cc]) = ph;
            *reinterpret_cast<uint2*>(&sXl[r * S + cc]) = pl;
        }
        __syncthreads();

        const int nb = tile * 64;
        const int next = tile + gridDim.x;
        if (next < ntiles) load_x(next);

        float acc[4][4];
#pragma unroll
        for (int nt = 0; nt < 4; ++nt)
#pragma unroll
            for (int t = 0; t < 4; ++t) acc[nt][t] = 0.f;

#pragma unroll
        for (int s = 0; s < 4; ++s) {
            const int k0 = s * 16;
            unsigned ah[4], al[4];
            {
                int r = warpm * 16 + g;
                ah[0] = *reinterpret_cast<const unsigned*>(&sXh[r * S + k0 + t2]);
                ah[1] = *reinterpret_cast<const unsigned*>(&sXh[(r + 8) * S + k0 + t2]);
                ah[2] = *reinterpret_cast<const unsigned*>(&sXh[r * S + k0 + t2 + 8]);
                ah[3] = *reinterpret_cast<const unsigned*>(&sXh[(r + 8) * S + k0 + t2 + 8]);
                al[0] = *reinterpret_cast<const unsigned*>(&sXl[r * S + k0 + t2]);
                al[1] = *reinterpret_cast<const unsigned*>(&sXl[(r + 8) * S + k0 + t2]);
                al[2] = *reinterpret_cast<const unsigned*>(&sXl[r * S + k0 + t2 + 8]);
                al[3] = *reinterpret_cast<const unsigned*>(&sXl[(r + 8) * S + k0 + t2 + 8]);
            }
#pragma unroll
            for (int nt = 0; nt < 4; ++nt) {
                int nn = warpn * 32 + nt * 8 + g;
                unsigned bh0 = *reinterpret_cast<const unsigned*>(&sWh[nn * S + k0 + t2]);
                unsigned bh1 = *reinterpret_cast<const unsigned*>(&sWh[nn * S + k0 + t2 + 8]);
                unsigned bl0 = *reinterpret_cast<const unsigned*>(&sWl[nn * S + k0 + t2]);
                unsigned bl1 = *reinterpret_cast<const unsigned*>(&sWl[nn * S + k0 + t2 + 8]);
                mma16816(acc[nt], ah, bh0, bh1);
                mma16816(acc[nt], al, bh0, bh1);
                mma16816(acc[nt], ah, bl0, bl1);
            }
        }

#pragma unroll
        for (int nt = 0; nt < 4; ++nt) {
            int col = warpn * 32 + nt * 8 + t2;
            int node0 = nb + warpm * 16 + g;
            int node1 = node0 + 8;
            if (node0 < n) {
                float2 v = make_float2(acc[nt][0], acc[nt][1]);
                *reinterpret_cast<float2*>(&ylr[(size_t)node0 * 64 + col]) = v;
            }
            if (node1 < n) {
                float2 v = make_float2(acc[nt][2], acc[nt][3]);
                *reinterpret_cast<float2*>(&ylr[(size_t)node1 * 64 + col]) = v;
            }
        }

        __syncthreads();
        tile = next;
    }
}

// ---------------------------------------------------------------------------
// per-node projection for small layers
// ---------------------------------------------------------------------------
template <int K, int F>
__global__ void proj_pernode(const float* __restrict__ x, const float* __restrict__ wl,
                             const float* __restrict__ wr, float* __restrict__ ylr, int n) {
    constexpr int NC = 2 * F;
    __shared__ float sB[K * NC];
    for (int i = threadIdx.x; i < K * NC; i += blockDim.x) {
        int k = i / NC, j = i % NC;
        sB[i] = (j < F) ? wl[k * F + j] : wr[k * F + (j - F)];
    }
    __syncthreads();

    int node = blockIdx.x * blockDim.x + threadIdx.x;
    if (node >= n) return;

    float xv[K];
    const float4* xr = reinterpret_cast<const float4*>(x + (size_t)node * K);
#pragma unroll
    for (int c = 0; c < K / 4; ++c) {
        float4 v = xr[c];
        xv[c * 4 + 0] = v.x; xv[c * 4 + 1] = v.y; xv[c * 4 + 2] = v.z; xv[c * 4 + 3] = v.w;
    }
    float acc[NC];
#pragma unroll
    for (int j = 0; j < NC; ++j) acc[j] = 0.f;
#pragma unroll
    for (int k = 0; k < K; ++k) {
        float a = xv[k];
#pragma unroll
        for (int j = 0; j < NC; ++j) acc[j] = fmaf(a, sB[k * NC + j], acc[j]);
    }
    float4* o = reinterpret_cast<float4*>(ylr + (size_t)node * NC);
#pragma unroll
    for (int c = 0; c < NC / 4; ++c)
        o[c] = make_float4(acc[c * 4], acc[c * 4 + 1], acc[c * 4 + 2], acc[c * 4 + 3]);
}

__global__ void proj3_pernode(const float* __restrict__ x, const float* __restrict__ wl,
                              const float* __restrict__ wr, float* __restrict__ ylr3, int n) {
    __shared__ float swl[16 * 9];
    __shared__ float swr[16 * 9];
    for (int i = threadIdx.x; i < 144; i += blockDim.x) {
        swl[i] = wl[i];
        swr[i] = wr[i];
    }
    __syncthreads();

    int node = blockIdx.x * blockDim.x + threadIdx.x;
    if (node >= n) return;

    float xv[16];
    const float4* xr = reinterpret_cast<const float4*>(x + (size_t)node * 16);
#pragma unroll
    for (int c = 0; c < 4; ++c) {
        float4 v = xr[c];
        xv[c * 4 + 0] = v.x; xv[c * 4 + 1] = v.y; xv[c * 4 + 2] = v.z; xv[c * 4 + 3] = v.w;
    }
    float al[9], ar[9];
#pragma unroll
    for (int j = 0; j < 9; ++j) { al[j] = 0.f; ar[j] = 0.f; }
#pragma unroll
    for (int k = 0; k < 16; ++k) {
        float a = xv[k];
#pragma unroll
        for (int j = 0; j < 9; ++j) {
            al[j] = fmaf(a, swl[k * 9 + j], al[j]);
            ar[j] = fmaf(a, swr[k * 9 + j], ar[j]);
        }
    }
    float4* o = reinterpret_cast<float4*>(ylr3 + (size_t)node * 32);
    o[0] = make_float4(al[0], al[1], al[2], al[3]);
    o[1] = make_float4(al[4], al[5], al[6], al[7]);
    o[2] = make_float4(al[8], 0.f, 0.f, 0.f);
    o[3] = make_float4(0.f, 0.f, 0.f, 0.f);
    o[4] = make_float4(ar[0], ar[1], ar[2], ar[3]);
    o[5] = make_float4(ar[4], ar[5], ar[6], ar[7]);
    ylr3[(size_t)node * 32 + 24] = ar[8];
}

// ---------------------------------------------------------------------------
// gather + combine (fused): warp per node, shfl-distributed edge indices.
// Round-13 structure (counted loop, no break), deeper unroll for MLP.
// ---------------------------------------------------------------------------
template <int F, bool RELU>
__global__ void gather_combine(const float* __restrict__ ylr, const int* __restrict__ esrc,
                               const int* __restrict__ off, const int* __restrict__ cnt,
                               const float* __restrict__ bias, float* __restrict__ out, int n) {
    constexpr int CH = F / 4;
    constexpr int EPW = 32 / CH;
    int w = (blockIdx.x * blockDim.x + threadIdx.x) >> 5;
    if (w >= n) return;
    int lane = threadIdx.x & 31;
    int c = lane % CH, g = lane / CH;
    int start = __ldg(off + w), deg = __ldg(cnt + w);

    // preload up to 32 edge indices (one per lane, coalesced)
    int eidx = 0;
    if (lane < deg) eidx = __ldg(esrc + start + lane);

    float4 acc = make_float4(0.f, 0.f, 0.f, 0.f);
    const float4* y4 = reinterpret_cast<const float4*>(ylr);
    int dmain = deg < 32 ? deg : 32;

    // uniform loop bound -> shfl executed by all lanes; load predicated
#pragma unroll 8
    for (int j = 0; j < dmain; j += EPW) {
        int jj = j + g;
        int src_lane = jj < 31 ? jj : 31;
        int s = __shfl_sync(0xFFFFFFFFu, eidx, src_lane);
        if (jj < dmain) {
            float4 v = y4[(size_t)s * (F / 2) + c];
            acc.x += v.x; acc.y += v.y; acc.z += v.z; acc.w += v.w;
        }
    }
    // rare tail: deg > 32
    for (int j = 32 + g; j < deg; j += EPW) {
        int s = __ldg(esrc + start + j);
        float4 v = y4[(size_t)s * (F / 2) + c];
        acc.x += v.x; acc.y += v.y; acc.z += v.z; acc.w += v.w;
    }

#pragma unroll
    for (int st = 16; st >= CH; st >>= 1) {
        acc.x += __shfl_xor_sync(0xFFFFFFFFu, acc.x, st);
        acc.y += __shfl_xor_sync(0xFFFFFFFFu, acc.y, st);
        acc.z += __shfl_xor_sync(0xFFFFFFFFu, acc.z, st);
        acc.w += __shfl_xor_sync(0xFFFFFFFFu, acc.w, st);
    }
    if (lane < CH) {
        float iv = __frcp_rn(fmaxf((float)deg, 1.0f));
        float4 r = y4[(size_t)w * (F / 2) + (F / 4) + c];
        float4 b = reinterpret_cast<const float4*>(bias)[c];
        float4 v;
        v.x = fmaf(acc.x, iv, r.x) + b.x;
        v.y = fmaf(acc.y, iv, r.y) + b.y;
        v.z = fmaf(acc.z, iv, r.z) + b.z;
        v.w = fmaf(acc.w, iv, r.w) + b.w;
        if (RELU) {
            v.x = fmaxf(v.x, 0.f); v.y = fmaxf(v.y, 0.f);
            v.z = fmaxf(v.z, 0.f); v.w = fmaxf(v.w, 0.f);
        }
        reinterpret_cast<float4*>(out)[(size_t)w * CH + c] = v;
    }
}

__global__ void gather9(const float* __restrict__ ylr3, const int* __restrict__ esrc,
                        const int* __restrict__ off, const int* __restrict__ cnt,
                        const float* __restrict__ bias, float* __restrict__ out, int n) {
    int w = (blockIdx.x * blockDim.x + threadIdx.x) >> 5;
    if (w >= n) return;
    int lane = threadIdx.x & 31;
    int c = lane % 4, g = lane / 4;  // 8 edges per iter
    int start = __ldg(off + w), deg = __ldg(cnt + w);

    int eidx = 0;
    if (lane < deg) eidx = __ldg(esrc + start + lane);

    float4 acc = make_float4(0.f, 0.f, 0.f, 0.f);
    const float4* y4 = reinterpret_cast<const float4*>(ylr3);
    int dmain = deg < 32 ? deg : 32;

#pragma unroll 4
    for (int j = 0; j < dmain; j += 8) {
        int jj = j + g;
        int src_lane = jj < 31 ? jj : 31;
        int s = __shfl_sync(0xFFFFFFFFu, eidx, src_lane);
        if (jj < dmain) {
            float4 v = y4[(size_t)s * 8 + c];
            acc.x += v.x; acc.y += v.y; acc.z += v.z; acc.w += v.w;
        }
    }
    for (int j = 32 + g; j < deg; j += 8) {
        int s = __ldg(esrc + start + j);
        float4 v = y4[(size_t)s * 8 + c];
        acc.x += v.x; acc.y += v.y; acc.z += v.z; acc.w += v.w;
    }

#pragma unroll
    for (int st = 16; st >= 4; st >>= 1) {
        acc.x += __shfl_xor_sync(0xFFFFFFFFu, acc.x, st);
        acc.y += __shfl_xor_sync(0xFFFFFFFFu, acc.y, st);
        acc.z += __shfl_xor_sync(0xFFFFFFFFu, acc.z, st);
        acc.w += __shfl_xor_sync(0xFFFFFFFFu, acc.w, st);
    }
    if (lane < 4) {
        float iv = __frcp_rn(fmaxf((float)deg, 1.0f));
        float a[4] = {acc.x, acc.y, acc.z, acc.w};
#pragma unroll
        for (int t = 0; t < 4; ++t) {
            int j = c * 4 + t;
            if (j < 9) {
                float yr = ylr3[(size_t)w * 32 + 16 + j];
                out[(size_t)w * 9 + j] = fmaf(a[t], iv, yr + __ldg(bias + j));
            }
        }
    }
}

// ---------------------------------------------------------------------------
// launch
// ---------------------------------------------------------------------------
extern "C" void kernel_launch(void* const* d_in, const int* in_sizes, int n_in,
                              void* d_out, int out_size) {
    const float* emb = (const float*)d_in[0];
    const int* ei = (const int*)d_in[1];
    const float* wl0 = (const float*)d_in[3];
    const float* wr0 = (const float*)d_in[4];
    const float* b0  = (const float*)d_in[5];
    const float* wl1 = (const float*)d_in[6];
    const float* wr1 = (const float*)d_in[7];
    const float* b1  = (const float*)d_in[8];
    const float* wl2 = (const float*)d_in[9];
    const float* wr2 = (const float*)d_in[10];
    const float* b2  = (const float*)d_in[11];
    const float* wl3 = (const float*)d_in[12];
    const float* wr3 = (const float*)d_in[13];
    const float* b3  = (const float*)d_in[14];
    float* out = (float*)d_out;

    const int n = in_sizes[0] / 128;
    const int E = in_sizes[1] / 2;
    const int* src = ei;
    const int* dst = ei + E;

    float *ylr, *xbuf;
    unsigned short *wth, *wtl, *wth1, *wtl1;
    int *cnt, *off, *cur, *esrc, *bsum;
    cudaGetSymbolAddress((void**)&ylr, g_ylr);
    cudaGetSymbolAddress((void**)&xbuf, g_x);
    cudaGetSymbolAddress((void**)&wth, g_wth);
    cudaGetSymbolAddress((void**)&wtl, g_wtl);
    cudaGetSymbolAddress((void**)&wth1, g_wth1);
    cudaGetSymbolAddress((void**)&wtl1, g_wtl1);
    cudaGetSymbolAddress((void**)&cnt, g_cnt);
    cudaGetSymbolAddress((void**)&off, g_off);
    cudaGetSymbolAddress((void**)&cur, g_cur);
    cudaGetSymbolAddress((void**)&esrc, g_esrc);
    cudaGetSymbolAddress((void**)&bsum, g_bsum);

    auto cdiv = [](int a, int b) { return (a + b - 1) / b; };
    const int TB = 256;
    const int nb = cdiv(n, 512);

    const int SM_MMA0 = (2 * 64 * 136 + 2 * 128 * 136) * 2;  // 104448
    const int SM_MMA1 = (4 * 64 * 72) * 2;                   // 36864
    cudaFuncSetAttribute((const void*)mma_proj0,
                         cudaFuncAttributeMaxDynamicSharedMemorySize, SM_MMA0);
    cudaFuncSetAttribute((const void*)mma_proj1,
                         cudaFuncAttributeMaxDynamicSharedMemorySize, SM_MMA1);

    static cudaStream_t s2 = nullptr;
    static cudaEvent_t evFork = nullptr, evJoin = nullptr;
    if (!s2) {
        cudaStreamCreateWithFlags(&s2, cudaStreamNonBlocking);
        cudaEventCreateWithFlags(&evFork, cudaEventDisableTiming);
        cudaEventCreateWithFlags(&evJoin, cudaEventDisableTiming);
    }

    // ---- fork: CSR build + W1 conversion on s2 (hidden under proj0) ----
    cudaEventRecord(evFork, 0);
    cudaStreamWaitEvent(s2, evFork, 0);

    cvt_w1_kernel<<<16, 256, 0, s2>>>(wl1, wr1, wth1, wtl1);
    zero_int<<<cdiv(n, 512), 512, 0, s2>>>(cnt, n);
    hist_kernel<<<cdiv(E, 512), 512, 0, s2>>>(dst, cnt, E);
    scan_block<<<nb, 512, 0, s2>>>(cnt, off, bsum, n);
    scan_sums<<<1, 512, 0, s2>>>(bsum, nb);
    scan_add<<<nb, 512, 0, s2>>>(off, bsum, cur, n);
    fill_kernel<<<cdiv(E, 512), 512, 0, s2>>>(src, dst, cur, esrc, E);
    cudaEventRecord(evJoin, s2);

    // ---- main: layer-0 tensor-core GEMM (persistent) ----
    cvt_w_kernel<<<64, 256>>>(wl0, wr0, wth, wtl);
    mma_proj0<<<296, 256, SM_MMA0>>>(emb, wth, wtl, ylr, n, cdiv(n, 64));

    // ---- join ----
    cudaStreamWaitEvent(0, evJoin, 0);

    gather_combine<64, true><<<cdiv(n * 32, TB), TB>>>(ylr, esrc, off, cnt, b0, xbuf, n);

    mma_proj1<<<444, 256, SM_MMA1>>>(xbuf, wth1, wtl1, ylr, n, cdiv(n, 64));
    gather_combine<32, true><<<cdiv(n * 32, TB), TB>>>(ylr, esrc, off, cnt, b1, xbuf, n);

    proj_pernode<32, 16><<<cdiv(n, TB), TB>>>(xbuf, wl2, wr2, ylr, n);
    gather_combine<16, true><<<cdiv(n * 32, TB), TB>>>(ylr, esrc, off, cnt, b2, xbuf, n);

    proj3_pernode<<<cdiv(n, TB), TB>>>(xbuf, wl3, wr3, ylr, n);
    gather9<<<cdiv(n * 32, TB), TB>>>(ylr, esrc, off, cnt, b3, out, n);
}

// round 17
// speedup vs baseline: 1.0867x; 1.0123x over previous
#include <cuda_runtime.h>
#include <cuda_bf16.h>
#include <cuda_fp16.h>
#include <cstdint>

#define NMAX 100000
#define EMAX 600000

// Scratch (static device globals — allocation-free per harness rules)
__device__ __align__(16) float g_ylr[NMAX * 64];           // layer 2/3 [yl|yr] rows
__device__ __align__(16) float g_x[NMAX * 64];             // layer activations
__device__ __align__(16) unsigned short g_ylh[NMAX * 64];  // yl in fp16 (layers 0/1)
__device__ __align__(16) float g_yrr[NMAX * 64];           // yr in fp32 (layers 0/1)
__device__ __align__(16) unsigned short g_wth[128 * 128];  // W0 hi bf16, n-major [n][k]
__device__ __align__(16) unsigned short g_wtl[128 * 128];  // W0 lo bf16, n-major [n][k]
__device__ __align__(16) unsigned short g_wth1[64 * 64];   // W1 hi bf16, n-major [n][k]
__device__ __align__(16) unsigned short g_wtl1[64 * 64];   // W1 lo bf16, n-major [n][k]
__device__ int g_cnt[NMAX];
__device__ int g_off[NMAX];
__device__ int g_cur[NMAX];
__device__ int g_esrc[EMAX];
__device__ int g_bsum[512];

// ---------------------------------------------------------------------------
// CSR build
// ---------------------------------------------------------------------------
__global__ void zero_int(int* __restrict__ p, int n) {
    int i = blockIdx.x * blockDim.x + threadIdx.x;
    if (i < n) p[i] = 0;
}

__global__ void hist_kernel(const int* __restrict__ dst, int* __restrict__ cnt, int E) {
    int i = blockIdx.x * blockDim.x + threadIdx.x;
    if (i < E) atomicAdd(&cnt[dst[i]], 1);
}

__device__ __forceinline__ int block_exscan_512(int v, int tid, int* warp_sums, int* total) {
    int lane = tid & 31, wid = tid >> 5;
    int inc = v;
#pragma unroll
    for (int st = 1; st < 32; st <<= 1) {
        int t = __shfl_up_sync(0xFFFFFFFFu, inc, st);
        if (lane >= st) inc += t;
    }
    if (lane == 31) warp_sums[wid] = inc;
    __syncthreads();
    if (wid == 0) {
        int ws = (lane < 16) ? warp_sums[lane] : 0;
#pragma unroll
        for (int st = 1; st < 16; st <<= 1) {
            int t = __shfl_up_sync(0xFFFFFFFFu, ws, st);
            if (lane >= st) ws += t;
        }
        if (lane < 16) warp_sums[lane] = ws;
    }
    __syncthreads();
    int base = (wid > 0) ? warp_sums[wid - 1] : 0;
    if (total) *total = warp_sums[15];
    return base + inc - v;
}

__global__ void scan_block(const int* __restrict__ cnt, int* __restrict__ off,
                           int* __restrict__ bsum, int n) {
    __shared__ int ws[16];
    int i = blockIdx.x * 512 + threadIdx.x;
    int v = (i < n) ? cnt[i] : 0;
    int total;
    int ex = block_exscan_512(v, threadIdx.x, ws, &total);
    if (i < n) off[i] = ex;
    if (threadIdx.x == 0) bsum[blockIdx.x] = total;
}

__global__ void scan_sums(int* __restrict__ bsum, int nb) {
    __shared__ int ws[16];
    int v = (threadIdx.x < nb) ? bsum[threadIdx.x] : 0;
    int ex = block_exscan_512(v, threadIdx.x, ws, nullptr);
    if (threadIdx.x < nb) bsum[threadIdx.x] = ex;
}

__global__ void scan_add(int* __restrict__ off, const int* __restrict__ bsum,
                         int* __restrict__ cur, int n) {
    int i = blockIdx.x * 512 + threadIdx.x;
    if (i < n) {
        int o = off[i] + bsum[blockIdx.x];
        off[i] = o;
        cur[i] = o;
    }
}

__global__ void fill_kernel(const int* __restrict__ src, const int* __restrict__ dst,
                            int* __restrict__ cur, int* __restrict__ esrc, int E) {
    int e = blockIdx.x * blockDim.x + threadIdx.x;
    if (e < E) {
        int p = atomicAdd(&cur[dst[e]], 1);
        esrc[p] = src[e];
    }
}

// ---------------------------------------------------------------------------
// W conversions: combined [k][n] -> n-major bf16 hi/lo wt[n*K + k]
// ---------------------------------------------------------------------------
__global__ void cvt_w_kernel(const float* __restrict__ wl, const float* __restrict__ wr,
                             unsigned short* __restrict__ wth, unsigned short* __restrict__ wtl) {
    int i = blockIdx.x * blockDim.x + threadIdx.x;
    if (i >= 128 * 128) return;
    int nn = i >> 7, k = i & 127;
    float w = (nn < 64) ? wl[k * 64 + nn] : wr[k * 64 + (nn - 64)];
    __nv_bfloat16 h = __float2bfloat16(w);
    __nv_bfloat16 l = __float2bfloat16(w - __bfloat162float(h));
    wth[i] = *reinterpret_cast<unsigned short*>(&h);
    wtl[i] = *reinterpret_cast<unsigned short*>(&l);
}

__global__ void cvt_w1_kernel(const float* __restrict__ wl, const float* __restrict__ wr,
                              unsigned short* __restrict__ wth, unsigned short* __restrict__ wtl) {
    int i = blockIdx.x * blockDim.x + threadIdx.x;
    if (i >= 64 * 64) return;
    int nn = i >> 6, k = i & 63;
    float w = (nn < 32) ? wl[k * 32 + nn] : wr[k * 32 + (nn - 32)];
    __nv_bfloat16 h = __float2bfloat16(w);
    __nv_bfloat16 l = __float2bfloat16(w - __bfloat162float(h));
    wth[i] = *reinterpret_cast<unsigned short*>(&h);
    wtl[i] = *reinterpret_cast<unsigned short*>(&l);
}

// ---------------------------------------------------------------------------
// mma helpers
// ---------------------------------------------------------------------------
__device__ __forceinline__ void mma16816(float* d, const unsigned* a,
                                         unsigned b0, unsigned b1) {
    asm volatile(
        "mma.sync.aligned.m16n8k16.row.col.f32.bf16.bf16.f32 "
        "{%0,%1,%2,%3}, {%4,%5,%6,%7}, {%8,%9}, {%0,%1,%2,%3};"
        : "+f"(d[0]), "+f"(d[1]), "+f"(d[2]), "+f"(d[3])
        : "r"(a[0]), "r"(a[1]), "r"(a[2]), "r"(a[3]), "r"(b0), "r"(b1));
}

__device__ __forceinline__ unsigned pack2_hi(float a, float b) {
    __nv_bfloat162 t;
    t.x = __float2bfloat16(a);
    t.y = __float2bfloat16(b);
    return *reinterpret_cast<unsigned*>(&t);
}

// ---------------------------------------------------------------------------
// layer-0 tensor-core GEMM (persistent): yl -> fp16 g_ylh, yr -> fp32 g_yrr
// ---------------------------------------------------------------------------
__global__ void __launch_bounds__(256, 2)
mma_proj0(const float* __restrict__ x, const unsigned short* __restrict__ wth,
          const unsigned short* __restrict__ wtl, __half* __restrict__ ylh,
          float* __restrict__ yr, int n, int ntiles) {
    constexpr int S = 136;
    extern __shared__ __align__(16) unsigned short smu[];
    unsigned short* sXh = smu;              // [64][S]
    unsigned short* sXl = sXh + 64 * S;
    unsigned short* sWh = sXl + 64 * S;     // n-major [128][S]
    unsigned short* sWl = sWh + 128 * S;

    const int tid = threadIdx.x;
    const int lane = tid & 31;
    const int warp = tid >> 5;
    const int warpm = warp >> 1;
    const int warpn = warp & 1;
    const int g = lane >> 2;
    const int t2 = (lane & 3) * 2;

    for (int idx = tid; idx < 128 * 16; idx += 256) {
        int r = idx >> 4, c = (idx & 15) * 8;
        *reinterpret_cast<uint4*>(&sWh[r * S + c]) =
            *reinterpret_cast<const uint4*>(&wth[r * 128 + c]);
        *reinterpret_cast<uint4*>(&sWl[r * S + c]) =
            *reinterpret_cast<const uint4*>(&wtl[r * 128 + c]);
    }

    float4 xf[8];
    auto load_x = [&](int tile) {
        const int nb = tile * 64;
        const int mrem = n - nb;
#pragma unroll
        for (int i = 0; i < 8; ++i) {
            int idx = tid + i * 256;
            int r = idx >> 5, cc = (idx & 31) * 4;
            float4 v = make_float4(0.f, 0.f, 0.f, 0.f);
            if (r < mrem)
                v = *reinterpret_cast<const float4*>(&x[(size_t)(nb + r) * 128 + cc]);
            xf[i] = v;
        }
    };

    int tile = blockIdx.x;
    if (tile < ntiles) load_x(tile);

    while (tile < ntiles) {
#pragma unroll
        for (int i = 0; i < 8; ++i) {
            int idx = tid + i * 256;
            int r = idx >> 5, cc = (idx & 31) * 4;
            float4 v = xf[i];
            __nv_bfloat16 h0 = __float2bfloat16(v.x), h1 = __float2bfloat16(v.y);
            __nv_bfloat16 h2 = __float2bfloat16(v.z), h3 = __float2bfloat16(v.w);
            uint2 ph, pl;
            __nv_bfloat162 t;
            t.x = h0; t.y = h1; ph.x = *reinterpret_cast<unsigned*>(&t);
            t.x = h2; t.y = h3; ph.y = *reinterpret_cast<unsigned*>(&t);
            pl.x = pack2_hi(v.x - __bfloat162float(h0), v.y - __bfloat162float(h1));
            pl.y = pack2_hi(v.z - __bfloat162float(h2), v.w - __bfloat162float(h3));
            *reinterpret_cast<uint2*>(&sXh[r * S + cc]) = ph;
            *reinterpret_cast<uint2*>(&sXl[r * S + cc]) = pl;
        }
        __syncthreads();

        const int nb = tile * 64;
        const int next = tile + gridDim.x;
        if (next < ntiles) load_x(next);

        float acc[8][4];
#pragma unroll
        for (int nt = 0; nt < 8; ++nt)
#pragma unroll
            for (int t = 0; t < 4; ++t) acc[nt][t] = 0.f;

#pragma unroll
        for (int s = 0; s < 8; ++s) {
            const int k0 = s * 16;
            unsigned ah[4], al[4];
            {
                int r = warpm * 16 + g;
                ah[0] = *reinterpret_cast<const unsigned*>(&sXh[r * S + k0 + t2]);
                ah[1] = *reinterpret_cast<const unsigned*>(&sXh[(r + 8) * S + k0 + t2]);
                ah[2] = *reinterpret_cast<const unsigned*>(&sXh[r * S + k0 + t2 + 8]);
                ah[3] = *reinterpret_cast<const unsigned*>(&sXh[(r + 8) * S + k0 + t2 + 8]);
                al[0] = *reinterpret_cast<const unsigned*>(&sXl[r * S + k0 + t2]);
                al[1] = *reinterpret_cast<const unsigned*>(&sXl[(r + 8) * S + k0 + t2]);
                al[2] = *reinterpret_cast<const unsigned*>(&sXl[r * S + k0 + t2 + 8]);
                al[3] = *reinterpret_cast<const unsigned*>(&sXl[(r + 8) * S + k0 + t2 + 8]);
            }
#pragma unroll
            for (int nt = 0; nt < 8; ++nt) {
                int nn = warpn * 64 + nt * 8 + g;
                unsigned bh0 = *reinterpret_cast<const unsigned*>(&sWh[nn * S + k0 + t2]);
                unsigned bh1 = *reinterpret_cast<const unsigned*>(&sWh[nn * S + k0 + t2 + 8]);
                unsigned bl0 = *reinterpret_cast<const unsigned*>(&sWl[nn * S + k0 + t2]);
                unsigned bl1 = *reinterpret_cast<const unsigned*>(&sWl[nn * S + k0 + t2 + 8]);
                mma16816(acc[nt], ah, bh0, bh1);
                mma16816(acc[nt], al, bh0, bh1);
                mma16816(acc[nt], ah, bl0, bl1);
            }
        }

        // epilogue: warpn0 cols 0-63 = yl -> fp16; warpn1 cols 64-127 = yr -> fp32
#pragma unroll
        for (int nt = 0; nt < 8; ++nt) {
            int col = nt * 8 + t2;  // 0..63 within the warpn half
            int node0 = nb + warpm * 16 + g;
            int node1 = node0 + 8;
            if (warpn == 0) {
                if (node0 < n)
                    *reinterpret_cast<__half2*>(&ylh[(size_t)node0 * 64 + col]) =
                        __floats2half2_rn(acc[nt][0], acc[nt][1]);
                if (node1 < n)
                    *reinterpret_cast<__half2*>(&ylh[(size_t)node1 * 64 + col]) =
                        __floats2half2_rn(acc[nt][2], acc[nt][3]);
            } else {
                if (node0 < n)
                    *reinterpret_cast<float2*>(&yr[(size_t)node0 * 64 + col]) =
                        make_float2(acc[nt][0], acc[nt][1]);
                if (node1 < n)
                    *reinterpret_cast<float2*>(&yr[(size_t)node1 * 64 + col]) =
                        make_float2(acc[nt][2], acc[nt][3]);
            }
        }

        __syncthreads();
        tile = next;
    }
}

// ---------------------------------------------------------------------------
// layer-1 tensor-core GEMM (persistent): yl -> fp16 g_ylh, yr -> fp32 g_yrr
// ---------------------------------------------------------------------------
__global__ void __launch_bounds__(256, 3)
mma_proj1(const float* __restrict__ x, const unsigned short* __restrict__ wth,
          const unsigned short* __restrict__ wtl, __half* __restrict__ ylh,
          float* __restrict__ yr, int n, int ntiles) {
    constexpr int S = 72;
    extern __shared__ __align__(16) unsigned short smu[];
    unsigned short* sXh = smu;              // [64][S]
    unsigned short* sXl = sXh + 64 * S;
    unsigned short* sWh = sXl + 64 * S;     // n-major [64][S]
    unsigned short* sWl = sWh + 64 * S;

    const int tid = threadIdx.x;
    const int lane = tid & 31;
    const int warp = tid >> 5;
    const int warpm = warp >> 1;
    const int warpn = warp & 1;
    const int g = lane >> 2;
    const int t2 = (lane & 3) * 2;

    for (int idx = tid; idx < 64 * 8; idx += 256) {
        int r = idx >> 3, c = (idx & 7) * 8;
        *reinterpret_cast<uint4*>(&sWh[r * S + c]) =
            *reinterpret_cast<const uint4*>(&wth[r * 64 + c]);
        *reinterpret_cast<uint4*>(&sWl[r * S + c]) =
            *reinterpret_cast<const uint4*>(&wtl[r * 64 + c]);
    }

    float4 xf[4];
    auto load_x = [&](int tile) {
        const int nb = tile * 64;
        const int mrem = n - nb;
#pragma unroll
        for (int i = 0; i < 4; ++i) {
            int idx = tid + i * 256;
            int r = idx >> 4, cc = (idx & 15) * 4;
            float4 v = make_float4(0.f, 0.f, 0.f, 0.f);
            if (r < mrem)
                v = *reinterpret_cast<const float4*>(&x[(size_t)(nb + r) * 64 + cc]);
            xf[i] = v;
        }
    };

    int tile = blockIdx.x;
    if (tile < ntiles) load_x(tile);

    while (tile < ntiles) {
#pragma unroll
        for (int i = 0; i < 4; ++i) {
            int idx = tid + i * 256;
            int r = idx >> 4, cc = (idx & 15) * 4;
            float4 v = xf[i];
            __nv_bfloat16 h0 = __float2bfloat16(v.x), h1 = __float2bfloat16(v.y);
            __nv_bfloat16 h2 = __float2bfloat16(v.z), h3 = __float2bfloat16(v.w);
            uint2 ph, pl;
            __nv_bfloat162 t;
            t.x = h0; t.y = h1; ph.x = *reinterpret_cast<unsigned*>(&t);
            t.x = h2; t.y = h3; ph.y = *reinterpret_cast<unsigned*>(&t);
            pl.x = pack2_hi(v.x - __bfloat162float(h0), v.y - __bfloat162float(h1));
            pl.y = pack2_hi(v.z - __bfloat162float(h2), v.w - __bfloat162float(h3));
            *reinterpret_cast<uint2*>(&sXh[r * S + cc]) = ph;
            *reinterpret_cast<uint2*>(&sXl[r * S + cc]) = pl;
        }
        __syncthreads();

        const int nb = tile * 64;
        const int next = tile + gridDim.x;
        if (next < ntiles) load_x(next);

        float acc[4][4];
#pragma unroll
        for (int nt = 0; nt < 4; ++nt)
#pragma unroll
            for (int t = 0; t < 4; ++t) acc[nt][t] = 0.f;

#pragma unroll
        for (int s = 0; s < 4; ++s) {
            const int k0 = s * 16;
            unsigned ah[4], al[4];
            {
                int r = warpm * 16 + g;
                ah[0] = *reinterpret_cast<const unsigned*>(&sXh[r * S + k0 + t2]);
                ah[1] = *reinterpret_cast<const unsigned*>(&sXh[(r + 8) * S + k0 + t2]);
                ah[2] = *reinterpret_cast<const unsigned*>(&sXh[r * S + k0 + t2 + 8]);
                ah[3] = *reinterpret_cast<const unsigned*>(&sXh[(r + 8) * S + k0 + t2 + 8]);
                al[0] = *reinterpret_cast<const unsigned*>(&sXl[r * S + k0 + t2]);
                al[1] = *reinterpret_cast<const unsigned*>(&sXl[(r + 8) * S + k0 + t2]);
                al[2] = *reinterpret_cast<const unsigned*>(&sXl[r * S + k0 + t2 + 8]);
                al[3] = *reinterpret_cast<const unsigned*>(&sXl[(r + 8) * S + k0 + t2 + 8]);
            }
#pragma unroll
            for (int nt = 0; nt < 4; ++nt) {
                int nn = warpn * 32 + nt * 8 + g;
                unsigned bh0 = *reinterpret_cast<const unsigned*>(&sWh[nn * S + k0 + t2]);
                unsigned bh1 = *reinterpret_cast<const unsigned*>(&sWh[nn * S + k0 + t2 + 8]);
                unsigned bl0 = *reinterpret_cast<const unsigned*>(&sWl[nn * S + k0 + t2]);
                unsigned bl1 = *reinterpret_cast<const unsigned*>(&sWl[nn * S + k0 + t2 + 8]);
                mma16816(acc[nt], ah, bh0, bh1);
                mma16816(acc[nt], al, bh0, bh1);
                mma16816(acc[nt], ah, bl0, bl1);
            }
        }

        // epilogue: warpn0 cols 0-31 = yl -> fp16; warpn1 cols 32-63 = yr -> fp32
#pragma unroll
        for (int nt = 0; nt < 4; ++nt) {
            int col = nt * 8 + t2;  // 0..31 within half
            int node0 = nb + warpm * 16 + g;
            int node1 = node0 + 8;
            if (warpn == 0) {
                if (node0 < n)
                    *reinterpret_cast<__half2*>(&ylh[(size_t)node0 * 32 + col]) =
                        __floats2half2_rn(acc[nt][0], acc[nt][1]);
                if (node1 < n)
                    *reinterpret_cast<__half2*>(&ylh[(size_t)node1 * 32 + col]) =
                        __floats2half2_rn(acc[nt][2], acc[nt][3]);
            } else {
                if (node0 < n)
                    *reinterpret_cast<float2*>(&yr[(size_t)node0 * 32 + col]) =
                        make_float2(acc[nt][0], acc[nt][1]);
                if (node1 < n)
                    *reinterpret_cast<float2*>(&yr[(size_t)node1 * 32 + col]) =
                        make_float2(acc[nt][2], acc[nt][3]);
            }
        }

        __syncthreads();
        tile = next;
    }
}

// ---------------------------------------------------------------------------
// per-node projection for small layers (fp32 path, unchanged)
// ---------------------------------------------------------------------------
template <int K, int F>
__global__ void proj_pernode(const float* __restrict__ x, const float* __restrict__ wl,
                             const float* __restrict__ wr, float* __restrict__ ylr, int n) {
    constexpr int NC = 2 * F;
    __shared__ float sB[K * NC];
    for (int i = threadIdx.x; i < K * NC; i += blockDim.x) {
        int k = i / NC, j = i % NC;
        sB[i] = (j < F) ? wl[k * F + j] : wr[k * F + (j - F)];
    }
    __syncthreads();

    int node = blockIdx.x * blockDim.x + threadIdx.x;
    if (node >= n) return;

    float xv[K];
    const float4* xr = reinterpret_cast<const float4*>(x + (size_t)node * K);
#pragma unroll
    for (int c = 0; c < K / 4; ++c) {
        float4 v = xr[c];
        xv[c * 4 + 0] = v.x; xv[c * 4 + 1] = v.y; xv[c * 4 + 2] = v.z; xv[c * 4 + 3] = v.w;
    }
    float acc[NC];
#pragma unroll
    for (int j = 0; j < NC; ++j) acc[j] = 0.f;
#pragma unroll
    for (int k = 0; k < K; ++k) {
        float a = xv[k];
#pragma unroll
        for (int j = 0; j < NC; ++j) acc[j] = fmaf(a, sB[k * NC + j], acc[j]);
    }
    float4* o = reinterpret_cast<float4*>(ylr + (size_t)node * NC);
#pragma unroll
    for (int c = 0; c < NC / 4; ++c)
        o[c] = make_float4(acc[c * 4], acc[c * 4 + 1], acc[c * 4 + 2], acc[c * 4 + 3]);
}

__global__ void proj3_pernode(const float* __restrict__ x, const float* __restrict__ wl,
                              const float* __restrict__ wr, float* __restrict__ ylr3, int n) {
    __shared__ float swl[16 * 9];
    __shared__ float swr[16 * 9];
    for (int i = threadIdx.x; i < 144; i += blockDim.x) {
        swl[i] = wl[i];
        swr[i] = wr[i];
    }
    __syncthreads();

    int node = blockIdx.x * blockDim.x + threadIdx.x;
    if (node >= n) return;

    float xv[16];
    const float4* xr = reinterpret_cast<const float4*>(x + (size_t)node * 16);
#pragma unroll
    for (int c = 0; c < 4; ++c) {
        float4 v = xr[c];
        xv[c * 4 + 0] = v.x; xv[c * 4 + 1] = v.y; xv[c * 4 + 2] = v.z; xv[c * 4 + 3] = v.w;
    }
    float al[9], ar[9];
#pragma unroll
    for (int j = 0; j < 9; ++j) { al[j] = 0.f; ar[j] = 0.f; }
#pragma unroll
    for (int k = 0; k < 16; ++k) {
        float a = xv[k];
#pragma unroll
        for (int j = 0; j < 9; ++j) {
            al[j] = fmaf(a, swl[k * 9 + j], al[j]);
            ar[j] = fmaf(a, swr[k * 9 + j], ar[j]);
        }
    }
    float4* o = reinterpret_cast<float4*>(ylr3 + (size_t)node * 32);
    o[0] = make_float4(al[0], al[1], al[2], al[3]);
    o[1] = make_float4(al[4], al[5], al[6], al[7]);
    o[2] = make_float4(al[8], 0.f, 0.f, 0.f);
    o[3] = make_float4(0.f, 0.f, 0.f, 0.f);
    o[4] = make_float4(ar[0], ar[1], ar[2], ar[3]);
    o[5] = make_float4(ar[4], ar[5], ar[6], ar[7]);
    ylr3[(size_t)node * 32 + 24] = ar[8];
}

// ---------------------------------------------------------------------------
// gather64h: layer-0 aggregation from fp16 yl + fp32 yr. Warp per node.
// CH=8 lanes x 16B (8 halves) per edge, EPW=4.
// ---------------------------------------------------------------------------
__global__ void gather64h(const __half* __restrict__ ylh, const float* __restrict__ yr,
                          const int* __restrict__ esrc, const int* __restrict__ off,
                          const int* __restrict__ cnt, const float* __restrict__ bias,
                          float* __restrict__ out, int n) {
    int w = (blockIdx.x * blockDim.x + threadIdx.x) >> 5;
    if (w >= n) return;
    int lane = threadIdx.x & 31;
    int c = lane & 7, g = lane >> 3;
    int start = __ldg(off + w), deg = __ldg(cnt + w);

    int eidx = 0;
    if (lane < deg) eidx = __ldg(esrc + start + lane);

    float acc[8];
#pragma unroll
    for (int t = 0; t < 8; ++t) acc[t] = 0.f;
    const uint4* yh4 = reinterpret_cast<const uint4*>(ylh);
    int dmain = deg < 32 ? deg : 32;

#pragma unroll 8
    for (int j = 0; j < dmain; j += 4) {
        int jj = j + g;
        int src_lane = jj < 31 ? jj : 31;
        int s = __shfl_sync(0xFFFFFFFFu, eidx, src_lane);
        if (jj < dmain) {
            uint4 hv = __ldg(&yh4[(size_t)s * 8 + c]);
            const __half2* hp = reinterpret_cast<const __half2*>(&hv);
#pragma unroll
            for (int t = 0; t < 4; ++t) {
                float2 f = __half22float2(hp[t]);
                acc[2 * t] += f.x;
                acc[2 * t + 1] += f.y;
            }
        }
    }
    for (int j = 32 + g; j < deg; j += 4) {
        int s = __ldg(esrc + start + j);
        uint4 hv = __ldg(&yh4[(size_t)s * 8 + c]);
        const __half2* hp = reinterpret_cast<const __half2*>(&hv);
#pragma unroll
        for (int t = 0; t < 4; ++t) {
            float2 f = __half22float2(hp[t]);
            acc[2 * t] += f.x;
            acc[2 * t + 1] += f.y;
        }
    }

#pragma unroll
    for (int st = 16; st >= 8; st >>= 1)
#pragma unroll
        for (int t = 0; t < 8; ++t) acc[t] += __shfl_xor_sync(0xFFFFFFFFu, acc[t], st);

    if (lane < 8) {
        float iv = __frcp_rn(fmaxf((float)deg, 1.0f));
        const float4* yr4 = reinterpret_cast<const float4*>(yr + (size_t)w * 64);
        const float4* b4 = reinterpret_cast<const float4*>(bias);
        float4 r0 = yr4[c * 2], r1 = yr4[c * 2 + 1];
        float4 b0 = b4[c * 2], b1 = b4[c * 2 + 1];
        float4 o0, o1;
        o0.x = fmaxf(fmaf(acc[0], iv, r0.x) + b0.x, 0.f);
        o0.y = fmaxf(fmaf(acc[1], iv, r0.y) + b0.y, 0.f);
        o0.z = fmaxf(fmaf(acc[2], iv, r0.z) + b0.z, 0.f);
        o0.w = fmaxf(fmaf(acc[3], iv, r0.w) + b0.w, 0.f);
        o1.x = fmaxf(fmaf(acc[4], iv, r1.x) + b1.x, 0.f);
        o1.y = fmaxf(fmaf(acc[5], iv, r1.y) + b1.y, 0.f);
        o1.z = fmaxf(fmaf(acc[6], iv, r1.z) + b1.z, 0.f);
        o1.w = fmaxf(fmaf(acc[7], iv, r1.w) + b1.w, 0.f);
        float4* o = reinterpret_cast<float4*>(out + (size_t)w * 64);
        o[c * 2] = o0;
        o[c * 2 + 1] = o1;
    }
}

// ---------------------------------------------------------------------------
// gather32h: layer-1 aggregation from fp16 yl + fp32 yr. Warp per node.
// CH=4 lanes x 16B (8 halves) per edge, EPW=8.
// ---------------------------------------------------------------------------
__global__ void gather32h(const __half* __restrict__ ylh, const float* __restrict__ yr,
                          const int* __restrict__ esrc, const int* __restrict__ off,
                          const int* __restrict__ cnt, const float* __restrict__ bias,
                          float* __restrict__ out, int n) {
    int w = (blockIdx.x * blockDim.x + threadIdx.x) >> 5;
    if (w >= n) return;
    int lane = threadIdx.x & 31;
    int c = lane & 3, g = lane >> 2;
    int start = __ldg(off + w), deg = __ldg(cnt + w);

    int eidx = 0;
    if (lane < deg) eidx = __ldg(esrc + start + lane);

    float acc[8];
#pragma unroll
    for (int t = 0; t < 8; ++t) acc[t] = 0.f;
    const uint4* yh4 = reinterpret_cast<const uint4*>(ylh);
    int dmain = deg < 32 ? deg : 32;

#pragma unroll 4
    for (int j = 0; j < dmain; j += 8) {
        int jj = j + g;
        int src_lane = jj < 31 ? jj : 31;
        int s = __shfl_sync(0xFFFFFFFFu, eidx, src_lane);
        if (jj < dmain) {
            uint4 hv = __ldg(&yh4[(size_t)s * 4 + c]);
            const __half2* hp = reinterpret_cast<const __half2*>(&hv);
#pragma unroll
            for (int t = 0; t < 4; ++t) {
                float2 f = __half22float2(hp[t]);
                acc[2 * t] += f.x;
                acc[2 * t + 1] += f.y;
            }
        }
    }
    for (int j = 32 + g; j < deg; j += 8) {
        int s = __ldg(esrc + start + j);
        uint4 hv = __ldg(&yh4[(size_t)s * 4 + c]);
        const __half2* hp = reinterpret_cast<const __half2*>(&hv);
#pragma unroll
        for (int t = 0; t < 4; ++t) {
            float2 f = __half22float2(hp[t]);
            acc[2 * t] += f.x;
            acc[2 * t + 1] += f.y;
        }
    }

#pragma unroll
    for (int st = 16; st >= 4; st >>= 1)
#pragma unroll
        for (int t = 0; t < 8; ++t) acc[t] += __shfl_xor_sync(0xFFFFFFFFu, acc[t], st);

    if (lane < 4) {
        float iv = __frcp_rn(fmaxf((float)deg, 1.0f));
        const float4* yr4 = reinterpret_cast<const float4*>(yr + (size_t)w * 32);
        const float4* b4 = reinterpret_cast<const float4*>(bias);
        float4 r0 = yr4[c * 2], r1 = yr4[c * 2 + 1];
        float4 b0 = b4[c * 2], b1 = b4[c * 2 + 1];
        float4 o0, o1;
        o0.x = fmaxf(fmaf(acc[0], iv, r0.x) + b0.x, 0.f);
        o0.y = fmaxf(fmaf(acc[1], iv, r0.y) + b0.y, 0.f);
        o0.z = fmaxf(fmaf(acc[2], iv, r0.z) + b0.z, 0.f);
        o0.w = fmaxf(fmaf(acc[3], iv, r0.w) + b0.w, 0.f);
        o1.x = fmaxf(fmaf(acc[4], iv, r1.x) + b1.x, 0.f);
        o1.y = fmaxf(fmaf(acc[5], iv, r1.y) + b1.y, 0.f);
        o1.z = fmaxf(fmaf(acc[6], iv, r1.z) + b1.z, 0.f);
        o1.w = fmaxf(fmaf(acc[7], iv, r1.w) + b1.w, 0.f);
        float4* o = reinterpret_cast<float4*>(out + (size_t)w * 32);
        o[c * 2] = o0;
        o[c * 2 + 1] = o1;
    }
}

// ---------------------------------------------------------------------------
// gather + combine (fp32 path, layers 2): warp per node
// ---------------------------------------------------------------------------
template <int F, bool RELU>
__global__ void gather_combine(const float* __restrict__ ylr, const int* __restrict__ esrc,
                               const int* __restrict__ off, const int* __restrict__ cnt,
                               const float* __restrict__ bias, float* __restrict__ out, int n) {
    constexpr int CH = F / 4;
    constexpr int EPW = 32 / CH;
    int w = (blockIdx.x * blockDim.x + threadIdx.x) >> 5;
    if (w >= n) return;
    int lane = threadIdx.x & 31;
    int c = lane % CH, g = lane / CH;
    int start = __ldg(off + w), deg = __ldg(cnt + w);

    int eidx = 0;
    if (lane < deg) eidx = __ldg(esrc + start + lane);

    float4 acc = make_float4(0.f, 0.f, 0.f, 0.f);
    const float4* y4 = reinterpret_cast<const float4*>(ylr);
    int dmain = deg < 32 ? deg : 32;

#pragma unroll 8
    for (int j = 0; j < dmain; j += EPW) {
        int jj = j + g;
        int src_lane = jj < 31 ? jj : 31;
        int s = __shfl_sync(0xFFFFFFFFu, eidx, src_lane);
        if (jj < dmain) {
            float4 v = y4[(size_t)s * (F / 2) + c];
            acc.x += v.x; acc.y += v.y; acc.z += v.z; acc.w += v.w;
        }
    }
    for (int j = 32 + g; j < deg; j += EPW) {
        int s = __ldg(esrc + start + j);
        float4 v = y4[(size_t)s * (F / 2) + c];
        acc.x += v.x; acc.y += v.y; acc.z += v.z; acc.w += v.w;
    }

#pragma unroll
    for (int st = 16; st >= CH; st >>= 1) {
        acc.x += __shfl_xor_sync(0xFFFFFFFFu, acc.x, st);
        acc.y += __shfl_xor_sync(0xFFFFFFFFu, acc.y, st);
        acc.z += __shfl_xor_sync(0xFFFFFFFFu, acc.z, st);
        acc.w += __shfl_xor_sync(0xFFFFFFFFu, acc.w, st);
    }
    if (lane < CH) {
        float iv = __frcp_rn(fmaxf((float)deg, 1.0f));
        float4 r = y4[(size_t)w * (F / 2) + (F / 4) + c];
        float4 b = reinterpret_cast<const float4*>(bias)[c];
        float4 v;
        v.x = fmaf(acc.x, iv, r.x) + b.x;
        v.y = fmaf(acc.y, iv, r.y) + b.y;
        v.z = fmaf(acc.z, iv, r.z) + b.z;
        v.w = fmaf(acc.w, iv, r.w) + b.w;
        if (RELU) {
            v.x = fmaxf(v.x, 0.f); v.y = fmaxf(v.y, 0.f);
            v.z = fmaxf(v.z, 0.f); v.w = fmaxf(v.w, 0.f);
        }
        reinterpret_cast<float4*>(out)[(size_t)w * CH + c] = v;
    }
}

__global__ void gather9(const float* __restrict__ ylr3, const int* __restrict__ esrc,
                        const int* __restrict__ off, const int* __restrict__ cnt,
                        const float* __restrict__ bias, float* __restrict__ out, int n) {
    int w = (blockIdx.x * blockDim.x + threadIdx.x) >> 5;
    if (w >= n) return;
    int lane = threadIdx.x & 31;
    int c = lane % 4, g = lane / 4;
    int start = __ldg(off + w), deg = __ldg(cnt + w);

    int eidx = 0;
    if (lane < deg) eidx = __ldg(esrc + start + lane);

    float4 acc = make_float4(0.f, 0.f, 0.f, 0.f);
    const float4* y4 = reinterpret_cast<const float4*>(ylr3);
    int dmain = deg < 32 ? deg : 32;

#pragma unroll 4
    for (int j = 0; j < dmain; j += 8) {
        int jj = j + g;
        int src_lane = jj < 31 ? jj : 31;
        int s = __shfl_sync(0xFFFFFFFFu, eidx, src_lane);
        if (jj < dmain) {
            float4 v = y4[(size_t)s * 8 + c];
            acc.x += v.x; acc.y += v.y; acc.z += v.z; acc.w += v.w;
        }
    }
    for (int j = 32 + g; j < deg; j += 8) {
        int s = __ldg(esrc + start + j);
        float4 v = y4[(size_t)s * 8 + c];
        acc.x += v.x; acc.y += v.y; acc.z += v.z; acc.w += v.w;
    }

#pragma unroll
    for (int st = 16; st >= 4; st >>= 1) {
        acc.x += __shfl_xor_sync(0xFFFFFFFFu, acc.x, st);
        acc.y += __shfl_xor_sync(0xFFFFFFFFu, acc.y, st);
        acc.z += __shfl_xor_sync(0xFFFFFFFFu, acc.z, st);
        acc.w += __shfl_xor_sync(0xFFFFFFFFu, acc.w, st);
    }
    if (lane < 4) {
        float iv = __frcp_rn(fmaxf((float)deg, 1.0f));
        float a[4] = {acc.x, acc.y, acc.z, acc.w};
#pragma unroll
        for (int t = 0; t < 4; ++t) {
            int j = c * 4 + t;
            if (j < 9) {
                float yrv = ylr3[(size_t)w * 32 + 16 + j];
                out[(size_t)w * 9 + j] = fmaf(a[t], iv, yrv + __ldg(bias + j));
            }
        }
    }
}

// ---------------------------------------------------------------------------
// launch
// ---------------------------------------------------------------------------
extern "C" void kernel_launch(void* const* d_in, const int* in_sizes, int n_in,
                              void* d_out, int out_size) {
    const float* emb = (const float*)d_in[0];
    const int* ei = (const int*)d_in[1];
    const float* wl0 = (const float*)d_in[3];
    const float* wr0 = (const float*)d_in[4];
    const float* b0  = (const float*)d_in[5];
    const float* wl1 = (const float*)d_in[6];
    const float* wr1 = (const float*)d_in[7];
    const float* b1  = (const float*)d_in[8];
    const float* wl2 = (const float*)d_in[9];
    const float* wr2 = (const float*)d_in[10];
    const float* b2  = (const float*)d_in[11];
    const float* wl3 = (const float*)d_in[12];
    const float* wr3 = (const float*)d_in[13];
    const float* b3  = (const float*)d_in[14];
    float* out = (float*)d_out;

    const int n = in_sizes[0] / 128;
    const int E = in_sizes[1] / 2;
    const int* src = ei;
    const int* dst = ei + E;

    float *ylr, *xbuf, *yrr;
    __half* ylh;
    unsigned short *wth, *wtl, *wth1, *wtl1, *ylh_us;
    int *cnt, *off, *cur, *esrc, *bsum;
    cudaGetSymbolAddress((void**)&ylr, g_ylr);
    cudaGetSymbolAddress((void**)&xbuf, g_x);
    cudaGetSymbolAddress((void**)&ylh_us, g_ylh);
    cudaGetSymbolAddress((void**)&yrr, g_yrr);
    cudaGetSymbolAddress((void**)&wth, g_wth);
    cudaGetSymbolAddress((void**)&wtl, g_wtl);
    cudaGetSymbolAddress((void**)&wth1, g_wth1);
    cudaGetSymbolAddress((void**)&wtl1, g_wtl1);
    cudaGetSymbolAddress((void**)&cnt, g_cnt);
    cudaGetSymbolAddress((void**)&off, g_off);
    cudaGetSymbolAddress((void**)&cur, g_cur);
    cudaGetSymbolAddress((void**)&esrc, g_esrc);
    cudaGetSymbolAddress((void**)&bsum, g_bsum);
    ylh = reinterpret_cast<__half*>(ylh_us);

    auto cdiv = [](int a, int b) { return (a + b - 1) / b; };
    const int TB = 256;
    const int nb = cdiv(n, 512);

    const int SM_MMA0 = (2 * 64 * 136 + 2 * 128 * 136) * 2;  // 104448
    const int SM_MMA1 = (4 * 64 * 72) * 2;                   // 36864
    cudaFuncSetAttribute((const void*)mma_proj0,
                         cudaFuncAttributeMaxDynamicSharedMemorySize, SM_MMA0);
    cudaFuncSetAttribute((const void*)mma_proj1,
                         cudaFuncAttributeMaxDynamicSharedMemorySize, SM_MMA1);

    static cudaStream_t s2 = nullptr;
    static cudaEvent_t evFork = nullptr, evJoin = nullptr;
    if (!s2) {
        cudaStreamCreateWithFlags(&s2, cudaStreamNonBlocking);
        cudaEventCreateWithFlags(&evFork, cudaEventDisableTiming);
        cudaEventCreateWithFlags(&evJoin, cudaEventDisableTiming);
    }

    // ---- fork: CSR build + W1 conversion on s2 (hidden under proj0) ----
    cudaEventRecord(evFork, 0);
    cudaStreamWaitEvent(s2, evFork, 0);

    cvt_w1_kernel<<<16, 256, 0, s2>>>(wl1, wr1, wth1, wtl1);
    zero_int<<<cdiv(n, 512), 512, 0, s2>>>(cnt, n);
    hist_kernel<<<cdiv(E, 512), 512, 0, s2>>>(dst, cnt, E);
    scan_block<<<nb, 512, 0, s2>>>(cnt, off, bsum, n);
    scan_sums<<<1, 512, 0, s2>>>(bsum, nb);
    scan_add<<<nb, 512, 0, s2>>>(off, bsum, cur, n);
    fill_kernel<<<cdiv(E, 512), 512, 0, s2>>>(src, dst, cur, esrc, E);
    cudaEventRecord(evJoin, s2);

    // ---- main: layer-0 tensor-core GEMM (persistent, fp16 yl output) ----
    cvt_w_kernel<<<64, 256>>>(wl0, wr0, wth, wtl);
    mma_proj0<<<296, 256, SM_MMA0>>>(emb, wth, wtl, ylh, yrr, n, cdiv(n, 64));

    // ---- join ----
    cudaStreamWaitEvent(0, evJoin, 0);

    gather64h<<<cdiv(n * 32, TB), TB>>>(ylh, yrr, esrc, off, cnt, b0, xbuf, n);

    mma_proj1<<<444, 256, SM_MMA1>>>(xbuf, wth1, wtl1, ylh, yrr, n, cdiv(n, 64));
    gather32h<<<cdiv(n * 32, TB), TB>>>(ylh, yrr, esrc, off, cnt, b1, xbuf, n);

    proj_pernode<32, 16><<<cdiv(n, TB), TB>>>(xbuf, wl2, wr2, ylr, n);
    gather_combine<16, true><<<cdiv(n * 32, TB), TB>>>(ylr, esrc, off, cnt, b2, xbuf, n);

    proj3_pernode<<<cdiv(n, TB), TB>>>(xbuf, wl3, wr3, ylr, n);
    gather9<<<cdiv(n * 32, TB), TB>>>(ylr, esrc, off, cnt, b3, out, n);
}